// round 1
// baseline (speedup 1.0000x reference)
#include <cuda_runtime.h>
#include <math.h>

// Problem dims
#define T_TOK 512
#define DDIM 1024
#define FDIM 4096
#define NEXP 8
#define RLORA 16
#define NPAIR (T_TOK * 2)
#define SCALING 2.0f
#define EPS_RMS 1e-6f

// ---------------- scratch (device globals; no allocation allowed) -----------
__device__ float g_t[T_TOK * DDIM];           // normalized tokens  [T, D]
__device__ float g_base1[T_TOK * FDIM];       // t @ w1^T           [T, F]
__device__ float g_base3[T_TOK * FDIM];       // t @ w3^T           [T, F]
__device__ float g_act[NPAIR * FDIM];         // silu(h1)*h3        [P, F]
__device__ float g_etrup[NPAIR * 2 * RLORA];  // up LoRA t@a^T      [P, 2, R]
__device__ float g_etr2[NPAIR * RLORA];       // down LoRA act@a2^T [P, R]
__device__ int   g_topi[NPAIR];               // expert id per pair
__device__ float g_topw[NPAIR];               // routing weight per pair

// ---------------- kernel 1: RMSNorm ----------------------------------------
__global__ void rmsnorm_kernel(const float* __restrict__ x,
                               const float* __restrict__ nw) {
    int tok = blockIdx.x;
    int tid = threadIdx.x;  // 256 threads, one float4 each (D=1024)
    float4 v = ((const float4*)(x + (size_t)tok * DDIM))[tid];
    float ss = v.x * v.x + v.y * v.y + v.z * v.z + v.w * v.w;
#pragma unroll
    for (int o = 16; o; o >>= 1) ss += __shfl_xor_sync(0xffffffffu, ss, o);
    __shared__ float red[8];
    if ((tid & 31) == 0) red[tid >> 5] = ss;
    __syncthreads();
    float tot = 0.f;
#pragma unroll
    for (int i = 0; i < 8; ++i) tot += red[i];
    float sc = rsqrtf(tot / (float)DDIM + EPS_RMS);
    float4 w = ((const float4*)nw)[tid];
    float4 o = make_float4(v.x * sc * w.x, v.y * sc * w.y,
                           v.z * sc * w.z, v.w * sc * w.w);
    ((float4*)(g_t + (size_t)tok * DDIM))[tid] = o;
}

// ---------------- kernel 2: router (softmax -> top2 -> renorm) --------------
__global__ void router_kernel(const float* __restrict__ gw) {
    int tok = blockIdx.x;
    int warp = threadIdx.x >> 5, lane = threadIdx.x & 31;  // 8 warps = 8 experts
    const float4* trow = (const float4*)(g_t + (size_t)tok * DDIM);
    const float4* grow = (const float4*)(gw + (size_t)warp * DDIM);
    float s = 0.f;
    for (int i = lane; i < DDIM / 4; i += 32) {
        float4 a = trow[i], b = grow[i];
        s += a.x * b.x + a.y * b.y + a.z * b.z + a.w * b.w;
    }
#pragma unroll
    for (int o = 16; o; o >>= 1) s += __shfl_xor_sync(0xffffffffu, s, o);
    __shared__ float lg[NEXP];
    if (lane == 0) lg[warp] = s;
    __syncthreads();
    if (threadIdx.x == 0) {
        // top-2 with first-index tie preference (matches jax top_k)
        int i0 = 0;
#pragma unroll
        for (int i = 1; i < NEXP; ++i) if (lg[i] > lg[i0]) i0 = i;
        int i1 = (i0 == 0) ? 1 : 0;
#pragma unroll
        for (int i = 0; i < NEXP; ++i) if (i != i0 && lg[i] > lg[i1]) i1 = i;
        // softmax over all experts then renormalize over top-2 == softmax over top-2
        float e1 = expf(lg[i1] - lg[i0]);
        float inv = 1.f / (1.f + e1);
        g_topi[tok * 2 + 0] = i0;
        g_topi[tok * 2 + 1] = i1;
        g_topw[tok * 2 + 0] = inv;
        g_topw[tok * 2 + 1] = e1 * inv;
    }
}

// ---------------- shared GEMM core: C = A @ B^T (both K-major) --------------
#define BM 128
#define BN 128
#define BKK 8
#define TM 8
#define TN 8

__device__ __forceinline__ void gemm_core(const float* __restrict__ Ab,
                                          const float* __restrict__ Bb,
                                          int Kt, int kBeg, int kEnd,
                                          float (&acc)[TM][TN]) {
    __shared__ float As[BKK * BM];
    __shared__ float Bs[BKK * BN];
    const int tid = threadIdx.x;
    const int lRow = tid >> 1;          // 0..127
    const int lCol = (tid & 1) * 4;     // 0 or 4
    const int tRow = (tid >> 4) * TM;
    const int tCol = (tid & 15) * TN;
    for (int k0 = kBeg; k0 < kEnd; k0 += BKK) {
        float4 av = *(const float4*)(Ab + (size_t)lRow * Kt + k0 + lCol);
        float4 bv = *(const float4*)(Bb + (size_t)lRow * Kt + k0 + lCol);
        As[(lCol + 0) * BM + lRow] = av.x;
        As[(lCol + 1) * BM + lRow] = av.y;
        As[(lCol + 2) * BM + lRow] = av.z;
        As[(lCol + 3) * BM + lRow] = av.w;
        Bs[(lCol + 0) * BN + lRow] = bv.x;
        Bs[(lCol + 1) * BN + lRow] = bv.y;
        Bs[(lCol + 2) * BN + lRow] = bv.z;
        Bs[(lCol + 3) * BN + lRow] = bv.w;
        __syncthreads();
#pragma unroll
        for (int k = 0; k < BKK; ++k) {
            float rm[TM], rn[TN];
#pragma unroll
            for (int m = 0; m < TM; ++m) rm[m] = As[k * BM + tRow + m];
#pragma unroll
            for (int n = 0; n < TN; ++n) rn[n] = Bs[k * BN + tCol + n];
#pragma unroll
            for (int m = 0; m < TM; ++m)
#pragma unroll
                for (int n = 0; n < TN; ++n) acc[m][n] += rm[m] * rn[n];
        }
        __syncthreads();
    }
}

// ---------------- kernel 3: base up-projection GEMMs ------------------------
// grid (FDIM/BN=32, T_TOK/BM=4); which: 0 -> base1(w1), 1 -> base3(w3)
__global__ __launch_bounds__(256) void up_gemm_kernel(const float* __restrict__ W,
                                                      int which) {
    float acc[TM][TN] = {};
    const float* Ab = g_t + (size_t)blockIdx.y * BM * DDIM;
    const float* Bb = W + (size_t)blockIdx.x * BN * DDIM;
    gemm_core(Ab, Bb, DDIM, 0, DDIM, acc);
    float* Cdst = which ? g_base3 : g_base1;
    const int tRow = (threadIdx.x >> 4) * TM;
    const int tCol = (threadIdx.x & 15) * TN;
#pragma unroll
    for (int m = 0; m < TM; ++m) {
        size_t row = (size_t)blockIdx.y * BM + tRow + m;
        float4* cp = (float4*)(Cdst + row * FDIM + blockIdx.x * BN + tCol);
        cp[0] = make_float4(acc[m][0], acc[m][1], acc[m][2], acc[m][3]);
        cp[1] = make_float4(acc[m][4], acc[m][5], acc[m][6], acc[m][7]);
    }
}

// ---------------- kernel 4: up LoRA rank projections (t @ a^T) --------------
// grid NPAIR blocks, 256 threads = 8 warps; each warp does 4 of 32 rank-dots.
__global__ void etr_up_kernel(const float* __restrict__ a1,
                              const float* __restrict__ a3) {
    int p = blockIdx.x, tok = p >> 1, e = g_topi[p];
    int warp = threadIdx.x >> 5, lane = threadIdx.x & 31;
    const float4* trow = (const float4*)(g_t + (size_t)tok * DDIM);
#pragma unroll
    for (int j = 0; j < 4; ++j) {
        int idx = warp * 4 + j;
        int mat = idx >> 4, r = idx & 15;
        const float* A = mat ? a3 : a1;
        const float4* arow = (const float4*)(A + ((size_t)e * RLORA + r) * DDIM);
        float s = 0.f;
        for (int i = lane; i < DDIM / 4; i += 32) {
            float4 u = trow[i], v = arow[i];
            s += u.x * v.x + u.y * v.y + u.z * v.z + u.w * v.w;
        }
#pragma unroll
        for (int o = 16; o; o >>= 1) s += __shfl_xor_sync(0xffffffffu, s, o);
        if (lane == 0) g_etrup[p * 32 + mat * 16 + r] = s;
    }
}

// ---------------- kernel 5: LoRA expand + SwiGLU ----------------------------
// grid (NPAIR, FDIM/1024); thread handles 4 consecutive f.
__global__ void act_kernel(const float* __restrict__ b1w,
                           const float* __restrict__ b3w) {
    int p = blockIdx.x, tok = p >> 1, e = g_topi[p];
    __shared__ float s1[RLORA], s3[RLORA];
    if (threadIdx.x < 32) {
        float v = g_etrup[p * 32 + threadIdx.x];
        if (threadIdx.x < 16) s1[threadIdx.x] = v;
        else                  s3[threadIdx.x - 16] = v;
    }
    __syncthreads();
    int f0 = blockIdx.y * 1024 + threadIdx.x * 4;
    float4 bs1 = *(const float4*)(g_base1 + (size_t)tok * FDIM + f0);
    float4 bs3 = *(const float4*)(g_base3 + (size_t)tok * FDIM + f0);
    const float* p1 = (const float*)&bs1;
    const float* p3 = (const float*)&bs3;
    float4 outv;
    float* ov = (float*)&outv;
#pragma unroll
    for (int j = 0; j < 4; ++j) {
        int f = f0 + j;
        const float4* q1 = (const float4*)(b1w + ((size_t)e * FDIM + f) * RLORA);
        const float4* q3 = (const float4*)(b3w + ((size_t)e * FDIM + f) * RLORA);
        float l1 = 0.f, l3 = 0.f;
#pragma unroll
        for (int i = 0; i < 4; ++i) {
            float4 v1 = q1[i], v3 = q3[i];
            l1 += v1.x * s1[i * 4 + 0] + v1.y * s1[i * 4 + 1] +
                  v1.z * s1[i * 4 + 2] + v1.w * s1[i * 4 + 3];
            l3 += v3.x * s3[i * 4 + 0] + v3.y * s3[i * 4 + 1] +
                  v3.z * s3[i * 4 + 2] + v3.w * s3[i * 4 + 3];
        }
        float h1 = p1[j] + SCALING * l1;
        float h3 = p3[j] + SCALING * l3;
        ov[j] = (h1 / (1.f + expf(-h1))) * h3;  // silu(h1) * h3
    }
    *(float4*)(g_act + (size_t)p * FDIM + f0) = outv;
}

// ---------------- kernel 6: down LoRA rank projection (act @ a2^T) ----------
__global__ void etr2_kernel(const float* __restrict__ a2) {
    int p = blockIdx.x, e = g_topi[p];
    int warp = threadIdx.x >> 5, lane = threadIdx.x & 31;
    const float4* actr = (const float4*)(g_act + (size_t)p * FDIM);
#pragma unroll
    for (int j = 0; j < 2; ++j) {
        int r = warp * 2 + j;
        const float4* arow = (const float4*)(a2 + ((size_t)e * RLORA + r) * FDIM);
        float s = 0.f;
        for (int i = lane; i < FDIM / 4; i += 32) {
            float4 u = actr[i], v = arow[i];
            s += u.x * v.x + u.y * v.y + u.z * v.z + u.w * v.w;
        }
#pragma unroll
        for (int o = 16; o; o >>= 1) s += __shfl_xor_sync(0xffffffffu, s, o);
        if (lane == 0) g_etr2[p * RLORA + r] = s;
    }
}

// ---------------- kernel 7: down GEMM + LoRA + route-weight epilogue --------
// grid (DDIM/BN=8, NPAIR/BM=8, splitK=2) -> 128 blocks.
__global__ __launch_bounds__(256) void down_gemm_kernel(const float* __restrict__ W2,
                                                        const float* __restrict__ B2,
                                                        float* __restrict__ Out) {
    float acc[TM][TN] = {};
    int kBeg = blockIdx.z * (FDIM / 2);
    const float* Ab = g_act + (size_t)blockIdx.y * BM * FDIM;
    const float* Bb = W2 + (size_t)blockIdx.x * BN * FDIM;
    gemm_core(Ab, Bb, FDIM, kBeg, kBeg + FDIM / 2, acc);
    const int tRow = (threadIdx.x >> 4) * TM;
    const int tCol = (threadIdx.x & 15) * TN;
#pragma unroll
    for (int m = 0; m < TM; ++m) {
        int p = blockIdx.y * BM + tRow + m;
        int tok = p >> 1;
        float wgt = g_topw[p];
        int e = g_topi[p];
        float er[RLORA];
        if (blockIdx.z == 0) {
#pragma unroll
            for (int r = 0; r < RLORA; ++r) er[r] = g_etr2[p * RLORA + r];
        }
#pragma unroll
        for (int n = 0; n < TN; ++n) {
            int d = blockIdx.x * BN + tCol + n;
            float v = acc[m][n];
            if (blockIdx.z == 0) {  // add down-LoRA term exactly once
                const float4* b2v =
                    (const float4*)(B2 + ((size_t)e * DDIM + d) * RLORA);
                float lora = 0.f;
#pragma unroll
                for (int i = 0; i < 4; ++i) {
                    float4 bb = b2v[i];
                    lora += bb.x * er[i * 4 + 0] + bb.y * er[i * 4 + 1] +
                            bb.z * er[i * 4 + 2] + bb.w * er[i * 4 + 3];
                }
                v += SCALING * lora;
            }
            atomicAdd(&Out[(size_t)tok * DDIM + d], wgt * v);
        }
    }
}

// ---------------- launcher ---------------------------------------------------
extern "C" void kernel_launch(void* const* d_in, const int* in_sizes, int n_in,
                              void* d_out, int out_size) {
    const float* x      = (const float*)d_in[0];
    const float* norm_w = (const float*)d_in[1];
    const float* w1     = (const float*)d_in[2];
    const float* w3     = (const float*)d_in[3];
    const float* w2     = (const float*)d_in[4];
    const float* gate_w = (const float*)d_in[5];
    const float* a1     = (const float*)d_in[6];
    const float* b1     = (const float*)d_in[7];
    const float* a3     = (const float*)d_in[8];
    const float* b3     = (const float*)d_in[9];
    const float* a2     = (const float*)d_in[10];
    const float* b2     = (const float*)d_in[11];
    float* out = (float*)d_out;

    rmsnorm_kernel<<<T_TOK, 256>>>(x, norm_w);
    router_kernel<<<T_TOK, 256>>>(gate_w);
    up_gemm_kernel<<<dim3(FDIM / BN, T_TOK / BM), 256>>>(w1, 0);
    up_gemm_kernel<<<dim3(FDIM / BN, T_TOK / BM), 256>>>(w3, 1);
    etr_up_kernel<<<NPAIR, 256>>>(a1, a3);
    act_kernel<<<dim3(NPAIR, FDIM / 1024), 256>>>(b1, b3);
    etr2_kernel<<<NPAIR, 256>>>(a2);
    cudaMemsetAsync(d_out, 0, (size_t)out_size * sizeof(float));
    down_gemm_kernel<<<dim3(DDIM / BN, NPAIR / BM, 2), 256>>>(w2, b2, out);
}

// round 3
// speedup vs baseline: 2.3921x; 2.3921x over previous
#include <cuda_runtime.h>
#include <cuda_bf16.h>
#include <cstdint>
#include <math.h>

// Problem dims
#define T_TOK 512
#define DDIM 1024
#define FDIM 4096
#define NEXP 8
#define RLORA 16
#define NPAIR 1024
#define SCALING 2.0f
#define EPS_RMS 1e-6f

// ---------------- scratch (device globals) ----------------------------------
__device__ float g_t[T_TOK * DDIM];
__device__ __nv_bfloat16 g_th[T_TOK * DDIM], g_tl[T_TOK * DDIM];
__device__ __nv_bfloat16 g_w1h[FDIM * DDIM], g_w1l[FDIM * DDIM];
__device__ __nv_bfloat16 g_w3h[FDIM * DDIM], g_w3l[FDIM * DDIM];
__device__ __nv_bfloat16 g_w2h[DDIM * FDIM], g_w2l[DDIM * FDIM];
__device__ __nv_bfloat16 g_acth[NPAIR * FDIM], g_actl[NPAIR * FDIM];
__device__ float g_base1[T_TOK * FDIM];
__device__ float g_base3[T_TOK * FDIM];
__device__ float g_etrup[NPAIR * 2 * RLORA];
__device__ float g_etr2[NPAIR * RLORA];
__device__ int   g_topi[NPAIR];
__device__ float g_topw[NPAIR];

// ---------------- helpers ----------------------------------------------------
__device__ __forceinline__ uint32_t smem_u32(const void* p) {
    return (uint32_t)__cvta_generic_to_shared(p);
}

__device__ __forceinline__ void split4(float4 v, uint2& h, uint2& l) {
    __nv_bfloat16 hx = __float2bfloat16(v.x);
    __nv_bfloat16 hy = __float2bfloat16(v.y);
    __nv_bfloat16 hz = __float2bfloat16(v.z);
    __nv_bfloat16 hw = __float2bfloat16(v.w);
    __nv_bfloat16 lx = __float2bfloat16(v.x - __bfloat162float(hx));
    __nv_bfloat16 ly = __float2bfloat16(v.y - __bfloat162float(hy));
    __nv_bfloat16 lz = __float2bfloat16(v.z - __bfloat162float(hz));
    __nv_bfloat16 lw = __float2bfloat16(v.w - __bfloat162float(hw));
    h.x = ((uint32_t)__bfloat16_as_ushort(hy) << 16) | __bfloat16_as_ushort(hx);
    h.y = ((uint32_t)__bfloat16_as_ushort(hw) << 16) | __bfloat16_as_ushort(hz);
    l.x = ((uint32_t)__bfloat16_as_ushort(ly) << 16) | __bfloat16_as_ushort(lx);
    l.y = ((uint32_t)__bfloat16_as_ushort(lw) << 16) | __bfloat16_as_ushort(lz);
}

__device__ __forceinline__ void ldsm_x4(uint32_t (&r)[4], uint32_t a) {
    asm volatile("ldmatrix.sync.aligned.m8n8.x4.shared.b16 {%0,%1,%2,%3}, [%4];"
                 : "=r"(r[0]), "=r"(r[1]), "=r"(r[2]), "=r"(r[3]) : "r"(a));
}
__device__ __forceinline__ void ldsm_x2(uint32_t (&r)[2], uint32_t a) {
    asm volatile("ldmatrix.sync.aligned.m8n8.x2.shared.b16 {%0,%1}, [%2];"
                 : "=r"(r[0]), "=r"(r[1]) : "r"(a));
}
__device__ __forceinline__ void mma_bf16(float (&c)[4], const uint32_t (&a)[4],
                                         const uint32_t (&b)[2]) {
    asm volatile(
        "mma.sync.aligned.m16n8k16.row.col.f32.bf16.bf16.f32 "
        "{%0,%1,%2,%3}, {%4,%5,%6,%7}, {%8,%9}, {%0,%1,%2,%3};"
        : "+f"(c[0]), "+f"(c[1]), "+f"(c[2]), "+f"(c[3])
        : "r"(a[0]), "r"(a[1]), "r"(a[2]), "r"(a[3]), "r"(b[0]), "r"(b[1]));
}
__device__ __forceinline__ void cp16(uint32_t dst, const void* src) {
    asm volatile("cp.async.cg.shared.global [%0], [%1], 16;" :: "r"(dst), "l"(src));
}
__device__ __forceinline__ void cp_commit() {
    asm volatile("cp.async.commit_group;" ::: "memory");
}
__device__ __forceinline__ void cp_wait1() {
    asm volatile("cp.async.wait_group 1;" ::: "memory");
}
__device__ __forceinline__ void cp_wait0() {
    asm volatile("cp.async.wait_group 0;" ::: "memory");
}

// load ROWS x 64 bf16 tile into SW128-swizzled smem via cp.async
template <int ROWS>
__device__ __forceinline__ void load_tile(uint32_t sdst, const __nv_bfloat16* g,
                                          int ld, int tid) {
#pragma unroll
    for (int i = 0; i < ROWS * 8 / 256; ++i) {
        int idx = i * 256 + tid;
        int row = idx >> 3, ch = idx & 7;
        uint32_t dst = sdst + row * 128 + ((ch * 16) ^ ((row & 7) << 4));
        cp16(dst, g + (size_t)row * ld + ch * 8);
    }
}

// one K-chunk (64) of 3-split mma: acc += Ah*Bh + Ah*Bl + Al*Bh
template <int MT, int NT>
__device__ __forceinline__ void compute_chunk(uint32_t sAh, uint32_t sAl,
                                              uint32_t sBh, uint32_t sBl,
                                              int warpRow, int warpCol, int lane,
                                              float (&acc)[MT][NT][4]) {
    int mi = lane >> 3;
    int arow = warpRow + ((mi & 1) << 3) + (lane & 7);
    uint32_t axor = (uint32_t)((arow & 7) << 4);
    uint32_t aoff = (uint32_t)arow * 128;
    int akb = (mi >> 1) << 4;
    int brow = warpCol + (lane & 7);
    int bi = (lane >> 3) & 1;
    uint32_t bxor = (uint32_t)((brow & 7) << 4);
    uint32_t boff = (uint32_t)brow * 128;
    int bkb = bi << 4;
#pragma unroll
    for (int ks = 0; ks < 4; ++ks) {
        uint32_t af[MT][4], bh[NT][2], bl[NT][2];
        uint32_t ak = (uint32_t)((ks * 32 + akb) ^ axor);
        uint32_t bk = (uint32_t)((ks * 32 + bkb) ^ bxor);
#pragma unroll
        for (int i = 0; i < MT; ++i) ldsm_x4(af[i], sAh + aoff + i * 2048 + ak);
#pragma unroll
        for (int j = 0; j < NT; ++j) ldsm_x2(bh[j], sBh + boff + j * 1024 + bk);
#pragma unroll
        for (int i = 0; i < MT; ++i)
#pragma unroll
            for (int j = 0; j < NT; ++j) mma_bf16(acc[i][j], af[i], bh[j]);
#pragma unroll
        for (int j = 0; j < NT; ++j) ldsm_x2(bl[j], sBl + boff + j * 1024 + bk);
#pragma unroll
        for (int i = 0; i < MT; ++i)
#pragma unroll
            for (int j = 0; j < NT; ++j) mma_bf16(acc[i][j], af[i], bl[j]);
#pragma unroll
        for (int i = 0; i < MT; ++i) ldsm_x4(af[i], sAl + aoff + i * 2048 + ak);
#pragma unroll
        for (int i = 0; i < MT; ++i)
#pragma unroll
            for (int j = 0; j < NT; ++j) mma_bf16(acc[i][j], af[i], bh[j]);
    }
}

// ---------------- kernel: weight split ---------------------------------------
__global__ void split_kernel(const float* __restrict__ src, int which, int n4) {
    __nv_bfloat16 *hi, *lo;
    if (which == 0)      { hi = g_w1h; lo = g_w1l; }
    else if (which == 1) { hi = g_w3h; lo = g_w3l; }
    else                 { hi = g_w2h; lo = g_w2l; }
    for (int i = blockIdx.x * blockDim.x + threadIdx.x; i < n4;
         i += gridDim.x * blockDim.x) {
        float4 v = ((const float4*)src)[i];
        uint2 h, l;
        split4(v, h, l);
        ((uint2*)hi)[i] = h;
        ((uint2*)lo)[i] = l;
    }
}

// ---------------- kernel: RMSNorm (+ hi/lo emit) ------------------------------
__global__ void rmsnorm_kernel(const float* __restrict__ x,
                               const float* __restrict__ nw) {
    int tok = blockIdx.x;
    int tid = threadIdx.x;
    float4 v = ((const float4*)(x + (size_t)tok * DDIM))[tid];
    float ss = v.x * v.x + v.y * v.y + v.z * v.z + v.w * v.w;
#pragma unroll
    for (int o = 16; o; o >>= 1) ss += __shfl_xor_sync(0xffffffffu, ss, o);
    __shared__ float red[8];
    if ((tid & 31) == 0) red[tid >> 5] = ss;
    __syncthreads();
    float tot = 0.f;
#pragma unroll
    for (int i = 0; i < 8; ++i) tot += red[i];
    float sc = rsqrtf(tot / (float)DDIM + EPS_RMS);
    float4 w = ((const float4*)nw)[tid];
    float4 o = make_float4(v.x * sc * w.x, v.y * sc * w.y, v.z * sc * w.z,
                           v.w * sc * w.w);
    ((float4*)(g_t + (size_t)tok * DDIM))[tid] = o;
    uint2 h, l;
    split4(o, h, l);
    ((uint2*)g_th)[tok * 256 + tid] = h;
    ((uint2*)g_tl)[tok * 256 + tid] = l;
}

// ---------------- kernel: router ---------------------------------------------
__global__ void router_kernel(const float* __restrict__ gw) {
    int tok = blockIdx.x;
    int warp = threadIdx.x >> 5, lane = threadIdx.x & 31;
    const float4* trow = (const float4*)(g_t + (size_t)tok * DDIM);
    const float4* grow = (const float4*)(gw + (size_t)warp * DDIM);
    float s = 0.f;
    for (int i = lane; i < DDIM / 4; i += 32) {
        float4 a = trow[i], b = grow[i];
        s += a.x * b.x + a.y * b.y + a.z * b.z + a.w * b.w;
    }
#pragma unroll
    for (int o = 16; o; o >>= 1) s += __shfl_xor_sync(0xffffffffu, s, o);
    __shared__ float lg[NEXP];
    if (lane == 0) lg[warp] = s;
    __syncthreads();
    if (threadIdx.x == 0) {
        int i0 = 0;
#pragma unroll
        for (int i = 1; i < NEXP; ++i) if (lg[i] > lg[i0]) i0 = i;
        int i1 = (i0 == 0) ? 1 : 0;
#pragma unroll
        for (int i = 0; i < NEXP; ++i) if (i != i0 && lg[i] > lg[i1]) i1 = i;
        float e1 = expf(lg[i1] - lg[i0]);
        float inv = 1.f / (1.f + e1);
        g_topi[tok * 2 + 0] = i0;
        g_topi[tok * 2 + 1] = i1;
        g_topw[tok * 2 + 0] = inv;
        g_topw[tok * 2 + 1] = e1 * inv;
    }
}

// ---------------- kernel: up GEMMs (mma.sync bf16, 3-split) ------------------
// grid (FDIM/128=32, T_TOK/128=4, 2). C = t @ W^T.
#define UP_TA (128 * 128)
#define UP_TB (128 * 128)
#define UP_STAGE (2 * UP_TA + 2 * UP_TB)
__global__ __launch_bounds__(256) void up_mma_kernel() {
    extern __shared__ __align__(128) char smem[];
    const int tid = threadIdx.x;
    const int wid = tid >> 5, lane = tid & 31;
    const int warpRow = (wid >> 2) * 64, warpCol = (wid & 3) * 32;
    uint32_t sb = smem_u32(smem);

    const __nv_bfloat16* Ah = g_th + (size_t)blockIdx.y * 128 * DDIM;
    const __nv_bfloat16* Al = g_tl + (size_t)blockIdx.y * 128 * DDIM;
    const __nv_bfloat16* Bh = (blockIdx.z ? g_w3h : g_w1h) + (size_t)blockIdx.x * 128 * DDIM;
    const __nv_bfloat16* Bl = (blockIdx.z ? g_w3l : g_w1l) + (size_t)blockIdx.x * 128 * DDIM;

    float acc[4][4][4] = {};
    const int NC = DDIM / 64;  // 16

    // prologue: issue chunk 0 into stage 0
    {
        uint32_t s0 = sb;
        load_tile<128>(s0, Ah, DDIM, tid);
        load_tile<128>(s0 + UP_TA, Al, DDIM, tid);
        load_tile<128>(s0 + 2 * UP_TA, Bh, DDIM, tid);
        load_tile<128>(s0 + 2 * UP_TA + UP_TB, Bl, DDIM, tid);
        cp_commit();
    }
    for (int c = 0; c < NC; ++c) {
        if (c + 1 < NC) {
            uint32_t s1 = sb + ((c + 1) & 1) * UP_STAGE;
            load_tile<128>(s1, Ah + (c + 1) * 64, DDIM, tid);
            load_tile<128>(s1 + UP_TA, Al + (c + 1) * 64, DDIM, tid);
            load_tile<128>(s1 + 2 * UP_TA, Bh + (c + 1) * 64, DDIM, tid);
            load_tile<128>(s1 + 2 * UP_TA + UP_TB, Bl + (c + 1) * 64, DDIM, tid);
            cp_commit();
            cp_wait1();
        } else {
            cp_wait0();
        }
        __syncthreads();
        uint32_t s = sb + (c & 1) * UP_STAGE;
        compute_chunk<4, 4>(s, s + UP_TA, s + 2 * UP_TA, s + 2 * UP_TA + UP_TB,
                            warpRow, warpCol, lane, acc);
        __syncthreads();
    }

    float* dst = blockIdx.z ? g_base3 : g_base1;
    int grp = lane >> 2, q = lane & 3;
#pragma unroll
    for (int i = 0; i < 4; ++i) {
        int r0 = blockIdx.y * 128 + warpRow + i * 16 + grp;
#pragma unroll
        for (int j = 0; j < 4; ++j) {
            int col = blockIdx.x * 128 + warpCol + j * 8 + q * 2;
            float2 v0 = make_float2(acc[i][j][0], acc[i][j][1]);
            float2 v1 = make_float2(acc[i][j][2], acc[i][j][3]);
            *(float2*)(dst + (size_t)r0 * FDIM + col) = v0;
            *(float2*)(dst + (size_t)(r0 + 8) * FDIM + col) = v1;
        }
    }
}

// ---------------- kernel: up LoRA rank projections ---------------------------
__global__ void etr_up_kernel(const float* __restrict__ a1,
                              const float* __restrict__ a3) {
    int p = blockIdx.x, tok = p >> 1, e = g_topi[p];
    int warp = threadIdx.x >> 5, lane = threadIdx.x & 31;
    const float4* trow = (const float4*)(g_t + (size_t)tok * DDIM);
#pragma unroll
    for (int j = 0; j < 4; ++j) {
        int idx = warp * 4 + j;
        int mat = idx >> 4, r = idx & 15;
        const float* A = mat ? a3 : a1;
        const float4* arow = (const float4*)(A + ((size_t)e * RLORA + r) * DDIM);
        float s = 0.f;
        for (int i = lane; i < DDIM / 4; i += 32) {
            float4 u = trow[i], v = arow[i];
            s += u.x * v.x + u.y * v.y + u.z * v.z + u.w * v.w;
        }
#pragma unroll
        for (int o = 16; o; o >>= 1) s += __shfl_xor_sync(0xffffffffu, s, o);
        if (lane == 0) g_etrup[p * 32 + mat * 16 + r] = s;
    }
}

// ---------------- kernel: LoRA expand + SwiGLU (emit bf16 hi/lo) -------------
__global__ void act_kernel(const float* __restrict__ b1w,
                           const float* __restrict__ b3w) {
    int p = blockIdx.x, tok = p >> 1, e = g_topi[p];
    __shared__ float s1[RLORA], s3[RLORA];
    if (threadIdx.x < 32) {
        float v = g_etrup[p * 32 + threadIdx.x];
        if (threadIdx.x < 16) s1[threadIdx.x] = v;
        else                  s3[threadIdx.x - 16] = v;
    }
    __syncthreads();
    int f0 = blockIdx.y * 1024 + threadIdx.x * 4;
    float4 bs1 = *(const float4*)(g_base1 + (size_t)tok * FDIM + f0);
    float4 bs3 = *(const float4*)(g_base3 + (size_t)tok * FDIM + f0);
    const float* p1 = (const float*)&bs1;
    const float* p3 = (const float*)&bs3;
    float4 outv;
    float* ov = (float*)&outv;
#pragma unroll
    for (int j = 0; j < 4; ++j) {
        int f = f0 + j;
        const float4* q1 = (const float4*)(b1w + ((size_t)e * FDIM + f) * RLORA);
        const float4* q3 = (const float4*)(b3w + ((size_t)e * FDIM + f) * RLORA);
        float l1 = 0.f, l3 = 0.f;
#pragma unroll
        for (int i = 0; i < 4; ++i) {
            float4 v1 = q1[i], v3 = q3[i];
            l1 += v1.x * s1[i * 4 + 0] + v1.y * s1[i * 4 + 1] +
                  v1.z * s1[i * 4 + 2] + v1.w * s1[i * 4 + 3];
            l3 += v3.x * s3[i * 4 + 0] + v3.y * s3[i * 4 + 1] +
                  v3.z * s3[i * 4 + 2] + v3.w * s3[i * 4 + 3];
        }
        float h1 = p1[j] + SCALING * l1;
        float h3 = p3[j] + SCALING * l3;
        ov[j] = (h1 / (1.f + expf(-h1))) * h3;
    }
    uint2 h, l;
    split4(outv, h, l);
    int i4 = ((size_t)p * FDIM + f0) >> 2;
    ((uint2*)g_acth)[i4] = h;
    ((uint2*)g_actl)[i4] = l;
}

// ---------------- kernel: down LoRA rank projection --------------------------
__global__ void etr2_kernel(const float* __restrict__ a2) {
    int p = blockIdx.x, e = g_topi[p];
    int warp = threadIdx.x >> 5, lane = threadIdx.x & 31;
    const uint2* ah = (const uint2*)(g_acth + (size_t)p * FDIM);
    const uint2* al = (const uint2*)(g_actl + (size_t)p * FDIM);
#pragma unroll
    for (int j = 0; j < 2; ++j) {
        int r = warp * 2 + j;
        const float4* arow = (const float4*)(a2 + ((size_t)e * RLORA + r) * FDIM);
        float s = 0.f;
        for (int i = lane; i < FDIM / 4; i += 32) {
            uint2 hv = ah[i], lv = al[i];
            float2 h01 = __bfloat1622float2(*(__nv_bfloat162*)&hv.x);
            float2 h23 = __bfloat1622float2(*(__nv_bfloat162*)&hv.y);
            float2 l01 = __bfloat1622float2(*(__nv_bfloat162*)&lv.x);
            float2 l23 = __bfloat1622float2(*(__nv_bfloat162*)&lv.y);
            float4 v = arow[i];
            s += (h01.x + l01.x) * v.x + (h01.y + l01.y) * v.y +
                 (h23.x + l23.x) * v.z + (h23.y + l23.y) * v.w;
        }
#pragma unroll
        for (int o = 16; o; o >>= 1) s += __shfl_xor_sync(0xffffffffu, s, o);
        if (lane == 0) g_etr2[p * RLORA + r] = s;
    }
}

// ---------------- kernel: down GEMM + fused epilogue -------------------------
// grid (DDIM/64=16, NPAIR/128=8). out[tok][d] = sum over the token's 2 experts.
#define DN_TA (128 * 128)
#define DN_TB (64 * 128)
#define DN_STAGE (2 * DN_TA + 2 * DN_TB)
__global__ __launch_bounds__(256) void down_mma_kernel(const float* __restrict__ B2,
                                                       float* __restrict__ Out) {
    extern __shared__ __align__(128) char smem[];
    const int tid = threadIdx.x;
    const int wid = tid >> 5, lane = tid & 31;
    const int warpRow = (wid >> 1) * 32, warpCol = (wid & 1) * 32;
    uint32_t sb = smem_u32(smem);

    const __nv_bfloat16* Ah = g_acth + (size_t)blockIdx.y * 128 * FDIM;
    const __nv_bfloat16* Al = g_actl + (size_t)blockIdx.y * 128 * FDIM;
    const __nv_bfloat16* Bh = g_w2h + (size_t)blockIdx.x * 64 * FDIM;
    const __nv_bfloat16* Bl = g_w2l + (size_t)blockIdx.x * 64 * FDIM;

    float acc[2][4][4] = {};
    const int NC = FDIM / 64;  // 64

    {
        uint32_t s0 = sb;
        load_tile<128>(s0, Ah, FDIM, tid);
        load_tile<128>(s0 + DN_TA, Al, FDIM, tid);
        load_tile<64>(s0 + 2 * DN_TA, Bh, FDIM, tid);
        load_tile<64>(s0 + 2 * DN_TA + DN_TB, Bl, FDIM, tid);
        cp_commit();
    }
    for (int c = 0; c < NC; ++c) {
        if (c + 1 < NC) {
            uint32_t s1 = sb + ((c + 1) & 1) * DN_STAGE;
            load_tile<128>(s1, Ah + (c + 1) * 64, FDIM, tid);
            load_tile<128>(s1 + DN_TA, Al + (c + 1) * 64, FDIM, tid);
            load_tile<64>(s1 + 2 * DN_TA, Bh + (c + 1) * 64, FDIM, tid);
            load_tile<64>(s1 + 2 * DN_TA + DN_TB, Bl + (c + 1) * 64, FDIM, tid);
            cp_commit();
            cp_wait1();
        } else {
            cp_wait0();
        }
        __syncthreads();
        uint32_t s = sb + (c & 1) * DN_STAGE;
        compute_chunk<2, 4>(s, s + DN_TA, s + 2 * DN_TA, s + 2 * DN_TA + DN_TB,
                            warpRow, warpCol, lane, acc);
        __syncthreads();
    }

    int grp = lane >> 2, q = lane & 3;
#pragma unroll
    for (int i = 0; i < 2; ++i) {
#pragma unroll
        for (int half = 0; half < 2; ++half) {
            int p = blockIdx.y * 128 + warpRow + i * 16 + grp + half * 8;
            int e = g_topi[p];
            float wgt = g_topw[p];
            float er[RLORA];
            {
                const float4* ep = (const float4*)(g_etr2 + p * RLORA);
#pragma unroll
                for (int k = 0; k < 4; ++k) {
                    float4 v = ep[k];
                    er[k * 4 + 0] = v.x; er[k * 4 + 1] = v.y;
                    er[k * 4 + 2] = v.z; er[k * 4 + 3] = v.w;
                }
            }
#pragma unroll
            for (int j = 0; j < 4; ++j) {
                int d = blockIdx.x * 64 + warpCol + j * 8 + q * 2;
                float vv[2];
#pragma unroll
                for (int c2 = 0; c2 < 2; ++c2) {
                    const float4* bb =
                        (const float4*)(B2 + ((size_t)e * DDIM + d + c2) * RLORA);
                    float lora = 0.f;
#pragma unroll
                    for (int k = 0; k < 4; ++k) {
                        float4 b4 = bb[k];
                        lora += b4.x * er[k * 4 + 0] + b4.y * er[k * 4 + 1] +
                                b4.z * er[k * 4 + 2] + b4.w * er[k * 4 + 3];
                    }
                    vv[c2] = (acc[i][j][half * 2 + c2] + SCALING * lora) * wgt;
                }
                float s0 = vv[0] + __shfl_down_sync(0xffffffffu, vv[0], 4);
                float s1 = vv[1] + __shfl_down_sync(0xffffffffu, vv[1], 4);
                if (!(grp & 1)) {
                    int tok = p >> 1;
                    *(float2*)(Out + (size_t)tok * DDIM + d) = make_float2(s0, s1);
                }
            }
        }
    }
}

// ---------------- launcher ---------------------------------------------------
extern "C" void kernel_launch(void* const* d_in, const int* in_sizes, int n_in,
                              void* d_out, int out_size) {
    const float* x      = (const float*)d_in[0];
    const float* norm_w = (const float*)d_in[1];
    const float* w1     = (const float*)d_in[2];
    const float* w3     = (const float*)d_in[3];
    const float* w2     = (const float*)d_in[4];
    const float* gate_w = (const float*)d_in[5];
    const float* a1     = (const float*)d_in[6];
    const float* b1     = (const float*)d_in[7];
    const float* a3     = (const float*)d_in[8];
    const float* b3     = (const float*)d_in[9];
    const float* a2     = (const float*)d_in[10];
    const float* b2     = (const float*)d_in[11];
    float* out = (float*)d_out;

    cudaFuncSetAttribute(up_mma_kernel,
                         cudaFuncAttributeMaxDynamicSharedMemorySize, 2 * UP_STAGE);
    cudaFuncSetAttribute(down_mma_kernel,
                         cudaFuncAttributeMaxDynamicSharedMemorySize, 2 * DN_STAGE);

    split_kernel<<<1024, 256>>>(w1, 0, FDIM * DDIM / 4);
    split_kernel<<<1024, 256>>>(w3, 1, FDIM * DDIM / 4);
    split_kernel<<<1024, 256>>>(w2, 2, DDIM * FDIM / 4);
    rmsnorm_kernel<<<T_TOK, 256>>>(x, norm_w);
    router_kernel<<<T_TOK, 256>>>(gate_w);
    up_mma_kernel<<<dim3(FDIM / 128, T_TOK / 128, 2), 256, 2 * UP_STAGE>>>();
    etr_up_kernel<<<NPAIR, 256>>>(a1, a3);
    act_kernel<<<dim3(NPAIR, FDIM / 1024), 256>>>(b1, b3);
    etr2_kernel<<<NPAIR, 256>>>(a2);
    down_mma_kernel<<<dim3(DDIM / 64, NPAIR / 128), 256, 2 * DN_STAGE>>>(b2, out);
}

// round 4
// speedup vs baseline: 3.6398x; 1.5216x over previous
#include <cuda_runtime.h>
#include <cuda_bf16.h>
#include <cstdint>
#include <math.h>

// Problem dims
#define T_TOK 512
#define DDIM 1024
#define FDIM 4096
#define NEXP 8
#define RLORA 16
#define NPAIR 1024
#define SCALING 2.0f
#define EPS_RMS 1e-6f
#define GSZ 32
#define MAXG 40

// ---------------- scratch (device globals) ----------------------------------
__device__ float g_t[T_TOK * DDIM];
__device__ __nv_bfloat16 g_th[T_TOK * DDIM], g_tl[T_TOK * DDIM];
__device__ __nv_bfloat16 g_w1h[FDIM * DDIM], g_w1l[FDIM * DDIM];
__device__ __nv_bfloat16 g_w3h[FDIM * DDIM], g_w3l[FDIM * DDIM];
__device__ __nv_bfloat16 g_w2h[DDIM * FDIM], g_w2l[DDIM * FDIM];
__device__ __nv_bfloat16 g_a2b[NEXP * RLORA * FDIM];
__device__ __nv_bfloat16 g_acth[NPAIR * FDIM], g_actl[NPAIR * FDIM];
__device__ __nv_bfloat16 g_ch[T_TOK * FDIM], g_cl[T_TOK * FDIM];
__device__ float g_base1[T_TOK * FDIM];
__device__ float g_base3[T_TOK * FDIM];
__device__ float g_etrup[NPAIR * 2 * RLORA];
__device__ float g_etr2[NPAIR * RLORA];
__device__ int   g_topi[NPAIR];
__device__ float g_topw[NPAIR];
__device__ int   g_sorted[NPAIR];
__device__ int   g_gstart[MAXG], g_glen[MAXG], g_gexp[MAXG];
__device__ int   g_ngroups;

// ---------------- helpers ----------------------------------------------------
__device__ __forceinline__ uint32_t smem_u32(const void* p) {
    return (uint32_t)__cvta_generic_to_shared(p);
}

__device__ __forceinline__ uint32_t packbf(float a, float b) {
    return ((uint32_t)__bfloat16_as_ushort(__float2bfloat16(b)) << 16) |
           __bfloat16_as_ushort(__float2bfloat16(a));
}
__device__ __forceinline__ void split4(float4 v, uint2& h, uint2& l) {
    __nv_bfloat16 hx = __float2bfloat16(v.x);
    __nv_bfloat16 hy = __float2bfloat16(v.y);
    __nv_bfloat16 hz = __float2bfloat16(v.z);
    __nv_bfloat16 hw = __float2bfloat16(v.w);
    h.x = ((uint32_t)__bfloat16_as_ushort(hy) << 16) | __bfloat16_as_ushort(hx);
    h.y = ((uint32_t)__bfloat16_as_ushort(hw) << 16) | __bfloat16_as_ushort(hz);
    l.x = packbf(v.x - __bfloat162float(hx), v.y - __bfloat162float(hy));
    l.y = packbf(v.z - __bfloat162float(hz), v.w - __bfloat162float(hw));
}
__device__ __forceinline__ float4 unpack_hl(uint2 h, uint2 l) {
    float2 h01 = __bfloat1622float2(*(__nv_bfloat162*)&h.x);
    float2 h23 = __bfloat1622float2(*(__nv_bfloat162*)&h.y);
    float2 l01 = __bfloat1622float2(*(__nv_bfloat162*)&l.x);
    float2 l23 = __bfloat1622float2(*(__nv_bfloat162*)&l.y);
    return make_float4(h01.x + l01.x, h01.y + l01.y, h23.x + l23.x, h23.y + l23.y);
}

__device__ __forceinline__ void ldsm_x4(uint32_t (&r)[4], uint32_t a) {
    asm volatile("ldmatrix.sync.aligned.m8n8.x4.shared.b16 {%0,%1,%2,%3}, [%4];"
                 : "=r"(r[0]), "=r"(r[1]), "=r"(r[2]), "=r"(r[3]) : "r"(a));
}
__device__ __forceinline__ void ldsm_x2(uint32_t (&r)[2], uint32_t a) {
    asm volatile("ldmatrix.sync.aligned.m8n8.x2.shared.b16 {%0,%1}, [%2];"
                 : "=r"(r[0]), "=r"(r[1]) : "r"(a));
}
__device__ __forceinline__ void mma_bf16(float (&c)[4], const uint32_t (&a)[4],
                                         const uint32_t (&b)[2]) {
    asm volatile(
        "mma.sync.aligned.m16n8k16.row.col.f32.bf16.bf16.f32 "
        "{%0,%1,%2,%3}, {%4,%5,%6,%7}, {%8,%9}, {%0,%1,%2,%3};"
        : "+f"(c[0]), "+f"(c[1]), "+f"(c[2]), "+f"(c[3])
        : "r"(a[0]), "r"(a[1]), "r"(a[2]), "r"(a[3]), "r"(b[0]), "r"(b[1]));
}
__device__ __forceinline__ void cp16(uint32_t dst, const void* src) {
    asm volatile("cp.async.cg.shared.global [%0], [%1], 16;" :: "r"(dst), "l"(src));
}
__device__ __forceinline__ void cp_commit() {
    asm volatile("cp.async.commit_group;" ::: "memory");
}
__device__ __forceinline__ void cp_wait1() {
    asm volatile("cp.async.wait_group 1;" ::: "memory");
}
__device__ __forceinline__ void cp_wait0() {
    asm volatile("cp.async.wait_group 0;" ::: "memory");
}

// load ROWS x 64 bf16 tile into SW128-swizzled smem via cp.async
template <int ROWS, int THREADS>
__device__ __forceinline__ void load_tile(uint32_t sdst, const __nv_bfloat16* g,
                                          int ld, int tid) {
#pragma unroll
    for (int i = 0; i < ROWS * 8 / THREADS; ++i) {
        int idx = i * THREADS + tid;
        int row = idx >> 3, ch = idx & 7;
        uint32_t dst = sdst + row * 128 + ((ch * 16) ^ ((row & 7) << 4));
        cp16(dst, g + (size_t)row * ld + ch * 8);
    }
}

// one K-chunk (64) of 3-split mma: acc += Ah*Bh + Ah*Bl + Al*Bh
template <int MT, int NT>
__device__ __forceinline__ void compute_chunk(uint32_t sAh, uint32_t sAl,
                                              uint32_t sBh, uint32_t sBl,
                                              int warpRow, int warpCol, int lane,
                                              float (&acc)[MT][NT][4]) {
    int mi = lane >> 3;
    int arow = warpRow + ((mi & 1) << 3) + (lane & 7);
    uint32_t axor = (uint32_t)((arow & 7) << 4);
    uint32_t aoff = (uint32_t)arow * 128;
    int akb = (mi >> 1) << 4;
    int brow = warpCol + (lane & 7);
    int bi = (lane >> 3) & 1;
    uint32_t bxor = (uint32_t)((brow & 7) << 4);
    uint32_t boff = (uint32_t)brow * 128;
    int bkb = bi << 4;
#pragma unroll
    for (int ks = 0; ks < 4; ++ks) {
        uint32_t af[MT][4], bh[NT][2], bl[NT][2];
        uint32_t ak = (uint32_t)((ks * 32 + akb) ^ axor);
        uint32_t bk = (uint32_t)((ks * 32 + bkb) ^ bxor);
#pragma unroll
        for (int i = 0; i < MT; ++i) ldsm_x4(af[i], sAh + aoff + i * 2048 + ak);
#pragma unroll
        for (int j = 0; j < NT; ++j) ldsm_x2(bh[j], sBh + boff + j * 1024 + bk);
#pragma unroll
        for (int i = 0; i < MT; ++i)
#pragma unroll
            for (int j = 0; j < NT; ++j) mma_bf16(acc[i][j], af[i], bh[j]);
#pragma unroll
        for (int j = 0; j < NT; ++j) ldsm_x2(bl[j], sBl + boff + j * 1024 + bk);
#pragma unroll
        for (int i = 0; i < MT; ++i)
#pragma unroll
            for (int j = 0; j < NT; ++j) mma_bf16(acc[i][j], af[i], bl[j]);
#pragma unroll
        for (int i = 0; i < MT; ++i) ldsm_x4(af[i], sAl + aoff + i * 2048 + ak);
#pragma unroll
        for (int i = 0; i < MT; ++i)
#pragma unroll
            for (int j = 0; j < NT; ++j) mma_bf16(acc[i][j], af[i], bl[j] /*unused*/),
                (void)0;
    }
}

// NOTE: the last pass above must use bh (Al*Bh), not bl. Correct version below.
#undef COMPUTE_CHUNK_BROKEN

template <int MT, int NT>
__device__ __forceinline__ void compute_chunk3(uint32_t sAh, uint32_t sAl,
                                               uint32_t sBh, uint32_t sBl,
                                               int warpRow, int warpCol, int lane,
                                               float (&acc)[MT][NT][4]) {
    int mi = lane >> 3;
    int arow = warpRow + ((mi & 1) << 3) + (lane & 7);
    uint32_t axor = (uint32_t)((arow & 7) << 4);
    uint32_t aoff = (uint32_t)arow * 128;
    int akb = (mi >> 1) << 4;
    int brow = warpCol + (lane & 7);
    int bi = (lane >> 3) & 1;
    uint32_t bxor = (uint32_t)((brow & 7) << 4);
    uint32_t boff = (uint32_t)brow * 128;
    int bkb = bi << 4;
#pragma unroll
    for (int ks = 0; ks < 4; ++ks) {
        uint32_t af[MT][4], bh[NT][2], bl[NT][2];
        uint32_t ak = (uint32_t)((ks * 32 + akb) ^ axor);
        uint32_t bk = (uint32_t)((ks * 32 + bkb) ^ bxor);
#pragma unroll
        for (int i = 0; i < MT; ++i) ldsm_x4(af[i], sAh + aoff + i * 2048 + ak);
#pragma unroll
        for (int j = 0; j < NT; ++j) ldsm_x2(bh[j], sBh + boff + j * 1024 + bk);
#pragma unroll
        for (int i = 0; i < MT; ++i)
#pragma unroll
            for (int j = 0; j < NT; ++j) mma_bf16(acc[i][j], af[i], bh[j]);
#pragma unroll
        for (int j = 0; j < NT; ++j) ldsm_x2(bl[j], sBl + boff + j * 1024 + bk);
#pragma unroll
        for (int i = 0; i < MT; ++i)
#pragma unroll
            for (int j = 0; j < NT; ++j) mma_bf16(acc[i][j], af[i], bl[j]);
#pragma unroll
        for (int i = 0; i < MT; ++i) ldsm_x4(af[i], sAl + aoff + i * 2048 + ak);
#pragma unroll
        for (int i = 0; i < MT; ++i)
#pragma unroll
            for (int j = 0; j < NT; ++j) mma_bf16(acc[i][j], af[i], bh[j]);
    }
}

// ---------------- kernel: weight split / cvt ---------------------------------
__global__ void split_kernel(const float* __restrict__ src, int which, int n4) {
    __nv_bfloat16 *hi, *lo;
    if (which == 0)      { hi = g_w1h; lo = g_w1l; }
    else if (which == 1) { hi = g_w3h; lo = g_w3l; }
    else                 { hi = g_w2h; lo = g_w2l; }
    for (int i = blockIdx.x * blockDim.x + threadIdx.x; i < n4;
         i += gridDim.x * blockDim.x) {
        float4 v = ((const float4*)src)[i];
        uint2 h, l;
        split4(v, h, l);
        ((uint2*)hi)[i] = h;
        ((uint2*)lo)[i] = l;
    }
}
__global__ void cvt_a2_kernel(const float* __restrict__ src) {
    int i = blockIdx.x * blockDim.x + threadIdx.x;
    const int n4 = NEXP * RLORA * FDIM / 4;
    if (i < n4) {
        float4 v = ((const float4*)src)[i];
        uint2 o;
        o.x = packbf(v.x, v.y);
        o.y = packbf(v.z, v.w);
        ((uint2*)g_a2b)[i] = o;
    }
}

// ---------------- kernel: RMSNorm (+ hi/lo emit) ------------------------------
__global__ void rmsnorm_kernel(const float* __restrict__ x,
                               const float* __restrict__ nw) {
    int tok = blockIdx.x;
    int tid = threadIdx.x;
    float4 v = ((const float4*)(x + (size_t)tok * DDIM))[tid];
    float ss = v.x * v.x + v.y * v.y + v.z * v.z + v.w * v.w;
#pragma unroll
    for (int o = 16; o; o >>= 1) ss += __shfl_xor_sync(0xffffffffu, ss, o);
    __shared__ float red[8];
    if ((tid & 31) == 0) red[tid >> 5] = ss;
    __syncthreads();
    float tot = 0.f;
#pragma unroll
    for (int i = 0; i < 8; ++i) tot += red[i];
    float sc = rsqrtf(tot / (float)DDIM + EPS_RMS);
    float4 w = ((const float4*)nw)[tid];
    float4 o = make_float4(v.x * sc * w.x, v.y * sc * w.y, v.z * sc * w.z,
                           v.w * sc * w.w);
    ((float4*)(g_t + (size_t)tok * DDIM))[tid] = o;
    uint2 h, l;
    split4(o, h, l);
    ((uint2*)g_th)[tok * 256 + tid] = h;
    ((uint2*)g_tl)[tok * 256 + tid] = l;
}

// ---------------- kernel: router ---------------------------------------------
__global__ void router_kernel(const float* __restrict__ gw) {
    int tok = blockIdx.x;
    int warp = threadIdx.x >> 5, lane = threadIdx.x & 31;
    const float4* trow = (const float4*)(g_t + (size_t)tok * DDIM);
    const float4* grow = (const float4*)(gw + (size_t)warp * DDIM);
    float s = 0.f;
    for (int i = lane; i < DDIM / 4; i += 32) {
        float4 a = trow[i], b = grow[i];
        s += a.x * b.x + a.y * b.y + a.z * b.z + a.w * b.w;
    }
#pragma unroll
    for (int o = 16; o; o >>= 1) s += __shfl_xor_sync(0xffffffffu, s, o);
    __shared__ float lg[NEXP];
    if (lane == 0) lg[warp] = s;
    __syncthreads();
    if (threadIdx.x == 0) {
        int i0 = 0;
#pragma unroll
        for (int i = 1; i < NEXP; ++i) if (lg[i] > lg[i0]) i0 = i;
        int i1 = (i0 == 0) ? 1 : 0;
#pragma unroll
        for (int i = 0; i < NEXP; ++i) if (i != i0 && lg[i] > lg[i1]) i1 = i;
        float e1 = expf(lg[i1] - lg[i0]);
        float inv = 1.f / (1.f + e1);
        g_topi[tok * 2 + 0] = i0;
        g_topi[tok * 2 + 1] = i1;
        g_topw[tok * 2 + 0] = inv;
        g_topw[tok * 2 + 1] = e1 * inv;
    }
}

// ---------------- kernel: expert-sort pairs ----------------------------------
__global__ void sort_kernel() {
    __shared__ int cnt[NEXP], ofs[NEXP + 1], cur[NEXP];
    int tid = threadIdx.x;
    if (tid < NEXP) cnt[tid] = 0;
    __syncthreads();
    for (int p = tid; p < NPAIR; p += 256) atomicAdd(&cnt[g_topi[p]], 1);
    __syncthreads();
    if (tid == 0) {
        ofs[0] = 0;
        for (int e = 0; e < NEXP; ++e) { ofs[e + 1] = ofs[e] + cnt[e]; cur[e] = ofs[e]; }
        int ng = 0;
        for (int e = 0; e < NEXP; ++e)
            for (int s = 0; s < cnt[e]; s += GSZ) {
                g_gstart[ng] = ofs[e] + s;
                g_glen[ng] = min(GSZ, cnt[e] - s);
                g_gexp[ng] = e;
                ng++;
            }
        g_ngroups = ng;
    }
    __syncthreads();
    for (int p = tid; p < NPAIR; p += 256) {
        int pos = atomicAdd(&cur[g_topi[p]], 1);
        g_sorted[pos] = p;
    }
}

// ---------------- kernel: up GEMMs (512 thr, 128x128 tile) -------------------
#define UP_T (128 * 64 * 2)
#define UP_STAGE (4 * UP_T)
__global__ __launch_bounds__(512) void up_mma_kernel() {
    extern __shared__ __align__(128) char smem[];
    const int tid = threadIdx.x;
    const int wid = tid >> 5, lane = tid & 31;
    const int warpRow = (wid >> 2) * 32, warpCol = (wid & 3) * 32;
    uint32_t sb = smem_u32(smem);

    const __nv_bfloat16* Ah = g_th + (size_t)blockIdx.y * 128 * DDIM;
    const __nv_bfloat16* Al = g_tl + (size_t)blockIdx.y * 128 * DDIM;
    const __nv_bfloat16* Bh = (blockIdx.z ? g_w3h : g_w1h) + (size_t)blockIdx.x * 128 * DDIM;
    const __nv_bfloat16* Bl = (blockIdx.z ? g_w3l : g_w1l) + (size_t)blockIdx.x * 128 * DDIM;

    float acc[2][4][4] = {};
    const int NC = DDIM / 64;

    {
        uint32_t s0 = sb;
        load_tile<128, 512>(s0, Ah, DDIM, tid);
        load_tile<128, 512>(s0 + UP_T, Al, DDIM, tid);
        load_tile<128, 512>(s0 + 2 * UP_T, Bh, DDIM, tid);
        load_tile<128, 512>(s0 + 3 * UP_T, Bl, DDIM, tid);
        cp_commit();
    }
    for (int c = 0; c < NC; ++c) {
        if (c + 1 < NC) {
            uint32_t s1 = sb + ((c + 1) & 1) * UP_STAGE;
            load_tile<128, 512>(s1, Ah + (c + 1) * 64, DDIM, tid);
            load_tile<128, 512>(s1 + UP_T, Al + (c + 1) * 64, DDIM, tid);
            load_tile<128, 512>(s1 + 2 * UP_T, Bh + (c + 1) * 64, DDIM, tid);
            load_tile<128, 512>(s1 + 3 * UP_T, Bl + (c + 1) * 64, DDIM, tid);
            cp_commit();
            cp_wait1();
        } else {
            cp_wait0();
        }
        __syncthreads();
        uint32_t s = sb + (c & 1) * UP_STAGE;
        compute_chunk3<2, 4>(s, s + UP_T, s + 2 * UP_T, s + 3 * UP_T,
                             warpRow, warpCol, lane, acc);
        __syncthreads();
    }

    float* dst = blockIdx.z ? g_base3 : g_base1;
    int grp = lane >> 2, q = lane & 3;
#pragma unroll
    for (int i = 0; i < 2; ++i) {
        int r0 = blockIdx.y * 128 + warpRow + i * 16 + grp;
#pragma unroll
        for (int j = 0; j < 4; ++j) {
            int col = blockIdx.x * 128 + warpCol + j * 8 + q * 2;
            *(float2*)(dst + (size_t)r0 * FDIM + col) =
                make_float2(acc[i][j][0], acc[i][j][1]);
            *(float2*)(dst + (size_t)(r0 + 8) * FDIM + col) =
                make_float2(acc[i][j][2], acc[i][j][3]);
        }
    }
}

// ---------------- kernel: up LoRA rank projections ---------------------------
__global__ void etr_up_kernel(const float* __restrict__ a1,
                              const float* __restrict__ a3) {
    int p = blockIdx.x, tok = p >> 1, e = g_topi[p];
    int warp = threadIdx.x >> 5, lane = threadIdx.x & 31;
    const float4* trow = (const float4*)(g_t + (size_t)tok * DDIM);
#pragma unroll
    for (int j = 0; j < 4; ++j) {
        int idx = warp * 4 + j;
        int mat = idx >> 4, r = idx & 15;
        const float* A = mat ? a3 : a1;
        const float4* arow = (const float4*)(A + ((size_t)e * RLORA + r) * DDIM);
        float s = 0.f;
        for (int i = lane; i < DDIM / 4; i += 32) {
            float4 u = trow[i], v = arow[i];
            s += u.x * v.x + u.y * v.y + u.z * v.z + u.w * v.w;
        }
#pragma unroll
        for (int o = 16; o; o >>= 1) s += __shfl_xor_sync(0xffffffffu, s, o);
        if (lane == 0) g_etrup[p * 32 + mat * 16 + r] = s;
    }
}

// ---------------- kernel: grouped LoRA expand + SwiGLU -----------------------
// grid (MAXG, 8). Each CTA: one expert-group x 512-f chunk; b rows in regs.
__global__ __launch_bounds__(256) void act_group_kernel(const float* __restrict__ b1w,
                                                        const float* __restrict__ b3w) {
    int gi = blockIdx.x;
    if (gi >= g_ngroups) return;
    int e = g_gexp[gi], start = g_gstart[gi], len = g_glen[gi];
    int tid = threadIdx.x;
    int f0 = blockIdx.y * 512 + tid * 2;
    __shared__ float sg[GSZ][32];
    __shared__ int sp[GSZ];
    for (int i = tid; i < len * 32; i += 256) {
        int k = i >> 5;
        sg[k][i & 31] = g_etrup[g_sorted[start + k] * 32 + (i & 31)];
    }
    if (tid < len) sp[tid] = g_sorted[start + tid];
    __syncthreads();

    float b1r[2][16], b3r[2][16];
#pragma unroll
    for (int fi = 0; fi < 2; ++fi) {
        const float4* q1 = (const float4*)(b1w + ((size_t)e * FDIM + f0 + fi) * RLORA);
        const float4* q3 = (const float4*)(b3w + ((size_t)e * FDIM + f0 + fi) * RLORA);
#pragma unroll
        for (int i = 0; i < 4; ++i) {
            float4 v1 = q1[i], v3 = q3[i];
            b1r[fi][i * 4 + 0] = v1.x; b1r[fi][i * 4 + 1] = v1.y;
            b1r[fi][i * 4 + 2] = v1.z; b1r[fi][i * 4 + 3] = v1.w;
            b3r[fi][i * 4 + 0] = v3.x; b3r[fi][i * 4 + 1] = v3.y;
            b3r[fi][i * 4 + 2] = v3.z; b3r[fi][i * 4 + 3] = v3.w;
        }
    }
    for (int k = 0; k < len; ++k) {
        int p = sp[k], tok = p >> 1;
        float2 bs1 = *(const float2*)(g_base1 + (size_t)tok * FDIM + f0);
        float2 bs3 = *(const float2*)(g_base3 + (size_t)tok * FDIM + f0);
        float hv[2];
#pragma unroll
        for (int fi = 0; fi < 2; ++fi) {
            float l1 = 0.f, l3 = 0.f;
#pragma unroll
            for (int r = 0; r < 16; ++r) {
                l1 += b1r[fi][r] * sg[k][r];
                l3 += b3r[fi][r] * sg[k][16 + r];
            }
            float h1 = (fi ? bs1.y : bs1.x) + SCALING * l1;
            float h3 = (fi ? bs3.y : bs3.x) + SCALING * l3;
            hv[fi] = (h1 / (1.f + expf(-h1))) * h3;
        }
        __nv_bfloat16 h0 = __float2bfloat16(hv[0]);
        __nv_bfloat16 h1b = __float2bfloat16(hv[1]);
        size_t idx = ((size_t)p * FDIM + f0) >> 1;
        ((uint32_t*)g_acth)[idx] =
            ((uint32_t)__bfloat16_as_ushort(h1b) << 16) | __bfloat16_as_ushort(h0);
        ((uint32_t*)g_actl)[idx] =
            packbf(hv[0] - __bfloat162float(h0), hv[1] - __bfloat162float(h1b));
    }
}

// ---------------- kernel: down LoRA rank projection (bf16 a2) ----------------
__global__ void etr2_kernel() {
    int p = blockIdx.x, e = g_topi[p];
    int warp = threadIdx.x >> 5, lane = threadIdx.x & 31;
    float sc = SCALING * g_topw[p];
    const uint2* ah = (const uint2*)(g_acth + (size_t)p * FDIM);
    const uint2* al = (const uint2*)(g_actl + (size_t)p * FDIM);
#pragma unroll
    for (int j = 0; j < 2; ++j) {
        int r = warp * 2 + j;
        const uint2* arow = (const uint2*)(g_a2b + ((size_t)e * RLORA + r) * FDIM);
        float s = 0.f;
        for (int i = lane; i < FDIM / 4; i += 32) {
            float4 act = unpack_hl(ah[i], al[i]);
            uint2 av = arow[i];
            float2 a01 = __bfloat1622float2(*(__nv_bfloat162*)&av.x);
            float2 a23 = __bfloat1622float2(*(__nv_bfloat162*)&av.y);
            s += act.x * a01.x + act.y * a01.y + act.z * a23.x + act.w * a23.y;
        }
#pragma unroll
        for (int o = 16; o; o >>= 1) s += __shfl_xor_sync(0xffffffffu, s, o);
        if (lane == 0) g_etr2[p * RLORA + r] = s * sc;
    }
}

// ---------------- kernel: weighted pair combine ------------------------------
// grid (T_TOK, 4). comb[t] = w0*act[2t] + w1*act[2t+1], emitted as bf16 hi/lo.
__global__ void combine_kernel() {
    int tok = blockIdx.x;
    int f0 = (blockIdx.y * 256 + threadIdx.x) * 4;
    float w0 = g_topw[tok * 2], w1 = g_topw[tok * 2 + 1];
    size_t i0 = ((size_t)(2 * tok) * FDIM + f0) >> 2;
    size_t i1 = i0 + (FDIM >> 2);
    float4 v0 = unpack_hl(((const uint2*)g_acth)[i0], ((const uint2*)g_actl)[i0]);
    float4 v1 = unpack_hl(((const uint2*)g_acth)[i1], ((const uint2*)g_actl)[i1]);
    float4 c = make_float4(w0 * v0.x + w1 * v1.x, w0 * v0.y + w1 * v1.y,
                           w0 * v0.z + w1 * v1.z, w0 * v0.w + w1 * v1.w);
    uint2 h, l;
    split4(c, h, l);
    size_t o = ((size_t)tok * FDIM + f0) >> 2;
    ((uint2*)g_ch)[o] = h;
    ((uint2*)g_cl)[o] = l;
}

// ---------------- kernel: down GEMM (64x64) + fused LoRA epilogue ------------
#define DN_T (64 * 64 * 2)
#define DN_STAGE (4 * DN_T)
__global__ __launch_bounds__(256) void down_mma_kernel(const float* __restrict__ B2,
                                                       float* __restrict__ Out) {
    extern __shared__ __align__(128) char smem[];
    const int tid = threadIdx.x;
    const int wid = tid >> 5, lane = tid & 31;
    const int warpRow = (wid >> 2) * 32, warpCol = (wid & 3) * 16;
    uint32_t sb = smem_u32(smem);

    const __nv_bfloat16* Ah = g_ch + (size_t)blockIdx.y * 64 * FDIM;
    const __nv_bfloat16* Al = g_cl + (size_t)blockIdx.y * 64 * FDIM;
    const __nv_bfloat16* Bh = g_w2h + (size_t)blockIdx.x * 64 * FDIM;
    const __nv_bfloat16* Bl = g_w2l + (size_t)blockIdx.x * 64 * FDIM;

    float acc[2][2][4] = {};
    const int NC = FDIM / 64;

    {
        uint32_t s0 = sb;
        load_tile<64, 256>(s0, Ah, FDIM, tid);
        load_tile<64, 256>(s0 + DN_T, Al, FDIM, tid);
        load_tile<64, 256>(s0 + 2 * DN_T, Bh, FDIM, tid);
        load_tile<64, 256>(s0 + 3 * DN_T, Bl, FDIM, tid);
        cp_commit();
    }
    for (int c = 0; c < NC; ++c) {
        if (c + 1 < NC) {
            uint32_t s1 = sb + ((c + 1) & 1) * DN_STAGE;
            load_tile<64, 256>(s1, Ah + (c + 1) * 64, FDIM, tid);
            load_tile<64, 256>(s1 + DN_T, Al + (c + 1) * 64, FDIM, tid);
            load_tile<64, 256>(s1 + 2 * DN_T, Bh + (c + 1) * 64, FDIM, tid);
            load_tile<64, 256>(s1 + 3 * DN_T, Bl + (c + 1) * 64, FDIM, tid);
            cp_commit();
            cp_wait1();
        } else {
            cp_wait0();
        }
        __syncthreads();
        uint32_t s = sb + (c & 1) * DN_STAGE;
        compute_chunk3<2, 2>(s, s + DN_T, s + 2 * DN_T, s + 3 * DN_T,
                             warpRow, warpCol, lane, acc);
        __syncthreads();
    }

    int grp = lane >> 2, q = lane & 3;
#pragma unroll
    for (int i = 0; i < 2; ++i) {
#pragma unroll
        for (int half = 0; half < 2; ++half) {
            int t = blockIdx.y * 64 + warpRow + i * 16 + half * 8 + grp;
            int p0 = 2 * t, p1 = 2 * t + 1;
            int e0 = g_topi[p0], e1 = g_topi[p1];
            float er0[16], er1[16];
            {
                const float4* q0 = (const float4*)(g_etr2 + p0 * RLORA);
                const float4* q1v = (const float4*)(g_etr2 + p1 * RLORA);
#pragma unroll
                for (int k = 0; k < 4; ++k) {
                    float4 a = q0[k], b = q1v[k];
                    er0[k * 4 + 0] = a.x; er0[k * 4 + 1] = a.y;
                    er0[k * 4 + 2] = a.z; er0[k * 4 + 3] = a.w;
                    er1[k * 4 + 0] = b.x; er1[k * 4 + 1] = b.y;
                    er1[k * 4 + 2] = b.z; er1[k * 4 + 3] = b.w;
                }
            }
#pragma unroll
            for (int j = 0; j < 2; ++j) {
                int d0 = blockIdx.x * 64 + warpCol + j * 8 + q * 2;
                float ov[2];
#pragma unroll
                for (int c2 = 0; c2 < 2; ++c2) {
                    int d = d0 + c2;
                    const float4* r0p = (const float4*)(B2 + ((size_t)e0 * DDIM + d) * RLORA);
                    const float4* r1p = (const float4*)(B2 + ((size_t)e1 * DDIM + d) * RLORA);
                    float dot = 0.f;
#pragma unroll
                    for (int k = 0; k < 4; ++k) {
                        float4 b0 = r0p[k], b1v = r1p[k];
                        dot += b0.x * er0[k * 4 + 0] + b0.y * er0[k * 4 + 1] +
                               b0.z * er0[k * 4 + 2] + b0.w * er0[k * 4 + 3];
                        dot += b1v.x * er1[k * 4 + 0] + b1v.y * er1[k * 4 + 1] +
                               b1v.z * er1[k * 4 + 2] + b1v.w * er1[k * 4 + 3];
                    }
                    ov[c2] = acc[i][j][half * 2 + c2] + dot;
                }
                *(float2*)(Out + (size_t)t * DDIM + d0) = make_float2(ov[0], ov[1]);
            }
        }
    }
}

// ---------------- launcher ---------------------------------------------------
extern "C" void kernel_launch(void* const* d_in, const int* in_sizes, int n_in,
                              void* d_out, int out_size) {
    const float* x      = (const float*)d_in[0];
    const float* norm_w = (const float*)d_in[1];
    const float* w1     = (const float*)d_in[2];
    const float* w3     = (const float*)d_in[3];
    const float* w2     = (const float*)d_in[4];
    const float* gate_w = (const float*)d_in[5];
    const float* a1     = (const float*)d_in[6];
    const float* b1     = (const float*)d_in[7];
    const float* a3     = (const float*)d_in[8];
    const float* b3     = (const float*)d_in[9];
    const float* a2     = (const float*)d_in[10];
    const float* b2     = (const float*)d_in[11];
    float* out = (float*)d_out;

    cudaFuncSetAttribute(up_mma_kernel,
                         cudaFuncAttributeMaxDynamicSharedMemorySize, 2 * UP_STAGE);
    cudaFuncSetAttribute(down_mma_kernel,
                         cudaFuncAttributeMaxDynamicSharedMemorySize, 2 * DN_STAGE);

    split_kernel<<<512, 256>>>(w1, 0, FDIM * DDIM / 4);
    split_kernel<<<512, 256>>>(w3, 1, FDIM * DDIM / 4);
    split_kernel<<<512, 256>>>(w2, 2, DDIM * FDIM / 4);
    cvt_a2_kernel<<<512, 256>>>(a2);
    rmsnorm_kernel<<<T_TOK, 256>>>(x, norm_w);
    router_kernel<<<T_TOK, 256>>>(gate_w);
    sort_kernel<<<1, 256>>>();
    up_mma_kernel<<<dim3(FDIM / 128, T_TOK / 128, 2), 512, 2 * UP_STAGE>>>();
    etr_up_kernel<<<NPAIR, 256>>>(a1, a3);
    act_group_kernel<<<dim3(MAXG, 8), 256>>>(b1, b3);
    etr2_kernel<<<NPAIR, 256>>>();
    combine_kernel<<<dim3(T_TOK, 4), 256>>>();
    down_mma_kernel<<<dim3(DDIM / 64, T_TOK / 64), 256, 2 * DN_STAGE>>>(b2, out);
}

// round 5
// speedup vs baseline: 4.0521x; 1.1133x over previous
#include <cuda_runtime.h>
#include <cuda_fp16.h>
#include <cstdint>
#include <math.h>

// Problem dims
#define T_TOK 512
#define DDIM 1024
#define FDIM 4096
#define NEXP 8
#define RLORA 16
#define NPAIR 1024
#define SCALING 2.0f
#define EPS_RMS 1e-6f
#define GSZ 32
#define MAXG 40

// ---------------- scratch (device globals) ----------------------------------
__device__ float g_t[T_TOK * DDIM];
__device__ __half g_th[T_TOK * DDIM], g_tl[T_TOK * DDIM];
__device__ __half g_w1h[FDIM * DDIM], g_w3h[FDIM * DDIM];
__device__ __half g_w2h[DDIM * FDIM];
__device__ __half g_a1h[NEXP * RLORA * DDIM], g_a3h[NEXP * RLORA * DDIM];
__device__ __half g_a2h[NEXP * RLORA * FDIM];
__device__ __half g_acth[NPAIR * FDIM];
__device__ __half g_ch[T_TOK * FDIM], g_cl[T_TOK * FDIM];
__device__ float g_base1[T_TOK * FDIM];
__device__ float g_base3[T_TOK * FDIM];
__device__ float g_etrup[NPAIR * 2 * RLORA];
__device__ float g_etr2[NPAIR * RLORA];
__device__ int   g_topi[NPAIR];
__device__ float g_topw[NPAIR];
__device__ int   g_sorted[NPAIR];
__device__ int   g_gstart[MAXG], g_glen[MAXG], g_gexp[MAXG];
__device__ int   g_ngroups;

// ---------------- helpers ----------------------------------------------------
__device__ __forceinline__ uint32_t smem_u32(const void* p) {
    return (uint32_t)__cvta_generic_to_shared(p);
}
__device__ __forceinline__ uint32_t packh(float a, float b) {
    return ((uint32_t)__half_as_ushort(__float2half_rn(b)) << 16) |
           __half_as_ushort(__float2half_rn(a));
}
__device__ __forceinline__ void split4h(float4 v, uint2& h, uint2& l) {
    __half hx = __float2half_rn(v.x), hy = __float2half_rn(v.y);
    __half hz = __float2half_rn(v.z), hw = __float2half_rn(v.w);
    h.x = ((uint32_t)__half_as_ushort(hy) << 16) | __half_as_ushort(hx);
    h.y = ((uint32_t)__half_as_ushort(hw) << 16) | __half_as_ushort(hz);
    l.x = packh(v.x - __half2float(hx), v.y - __half2float(hy));
    l.y = packh(v.z - __half2float(hz), v.w - __half2float(hw));
}
__device__ __forceinline__ float2 h22f2(uint32_t u) {
    return __half22float2(*(__half2*)&u);
}

__device__ __forceinline__ void ldsm_x4(uint32_t (&r)[4], uint32_t a) {
    asm volatile("ldmatrix.sync.aligned.m8n8.x4.shared.b16 {%0,%1,%2,%3}, [%4];"
                 : "=r"(r[0]), "=r"(r[1]), "=r"(r[2]), "=r"(r[3]) : "r"(a));
}
__device__ __forceinline__ void ldsm_x2(uint32_t (&r)[2], uint32_t a) {
    asm volatile("ldmatrix.sync.aligned.m8n8.x2.shared.b16 {%0,%1}, [%2];"
                 : "=r"(r[0]), "=r"(r[1]) : "r"(a));
}
__device__ __forceinline__ void mma_f16(float (&c)[4], const uint32_t (&a)[4],
                                        const uint32_t (&b)[2]) {
    asm volatile(
        "mma.sync.aligned.m16n8k16.row.col.f32.f16.f16.f32 "
        "{%0,%1,%2,%3}, {%4,%5,%6,%7}, {%8,%9}, {%0,%1,%2,%3};"
        : "+f"(c[0]), "+f"(c[1]), "+f"(c[2]), "+f"(c[3])
        : "r"(a[0]), "r"(a[1]), "r"(a[2]), "r"(a[3]), "r"(b[0]), "r"(b[1]));
}
__device__ __forceinline__ void cp16(uint32_t dst, const void* src) {
    asm volatile("cp.async.cg.shared.global [%0], [%1], 16;" :: "r"(dst), "l"(src));
}
__device__ __forceinline__ void cp_commit() {
    asm volatile("cp.async.commit_group;" ::: "memory");
}
__device__ __forceinline__ void cp_wait1() {
    asm volatile("cp.async.wait_group 1;" ::: "memory");
}
__device__ __forceinline__ void cp_wait0() {
    asm volatile("cp.async.wait_group 0;" ::: "memory");
}

// load ROWS x 64 fp16 tile into SW128-swizzled smem via cp.async
template <int ROWS, int THREADS>
__device__ __forceinline__ void load_tile(uint32_t sdst, const __half* g,
                                          int ld, int tid) {
#pragma unroll
    for (int i = 0; i < ROWS * 8 / THREADS; ++i) {
        int idx = i * THREADS + tid;
        int row = idx >> 3, ch = idx & 7;
        uint32_t dst = sdst + row * 128 + ((ch * 16) ^ ((row & 7) << 4));
        cp16(dst, g + (size_t)row * ld + ch * 8);
    }
}

// one K-chunk (64) of 2-pass mma: acc += Ah*Bh + Al*Bh  (A-quantization cancels)
template <int MT, int NT>
__device__ __forceinline__ void compute_chunk2(uint32_t sAh, uint32_t sAl,
                                               uint32_t sBh,
                                               int warpRow, int warpCol, int lane,
                                               float (&acc)[MT][NT][4]) {
    int mi = lane >> 3;
    int arow = warpRow + ((mi & 1) << 3) + (lane & 7);
    uint32_t axor = (uint32_t)((arow & 7) << 4);
    uint32_t aoff = (uint32_t)arow * 128;
    int akb = (mi >> 1) << 4;
    int brow = warpCol + (lane & 7);
    int bi = (lane >> 3) & 1;
    uint32_t bxor = (uint32_t)((brow & 7) << 4);
    uint32_t boff = (uint32_t)brow * 128;
    int bkb = bi << 4;
#pragma unroll
    for (int ks = 0; ks < 4; ++ks) {
        uint32_t af[MT][4], bh[NT][2];
        uint32_t ak = (uint32_t)((ks * 32 + akb) ^ axor);
        uint32_t bk = (uint32_t)((ks * 32 + bkb) ^ bxor);
#pragma unroll
        for (int i = 0; i < MT; ++i) ldsm_x4(af[i], sAh + aoff + i * 2048 + ak);
#pragma unroll
        for (int j = 0; j < NT; ++j) ldsm_x2(bh[j], sBh + boff + j * 1024 + bk);
#pragma unroll
        for (int i = 0; i < MT; ++i)
#pragma unroll
            for (int j = 0; j < NT; ++j) mma_f16(acc[i][j], af[i], bh[j]);
#pragma unroll
        for (int i = 0; i < MT; ++i) ldsm_x4(af[i], sAl + aoff + i * 2048 + ak);
#pragma unroll
        for (int i = 0; i < MT; ++i)
#pragma unroll
            for (int j = 0; j < NT; ++j) mma_f16(acc[i][j], af[i], bh[j]);
    }
}

// ---------------- kernel: fp32 -> fp16 conversions (all weights) -------------
#define N_W (FDIM * DDIM / 4)
#define N_A1 (NEXP * RLORA * DDIM / 4)
#define N_A2 (NEXP * RLORA * FDIM / 4)
__global__ void cvt_kernel(const float* __restrict__ w1, const float* __restrict__ w3,
                           const float* __restrict__ w2, const float* __restrict__ a1,
                           const float* __restrict__ a3, const float* __restrict__ a2) {
    const int total = 3 * N_W + 2 * N_A1 + N_A2;
    for (int i = blockIdx.x * blockDim.x + threadIdx.x; i < total;
         i += gridDim.x * blockDim.x) {
        int j = i;
        const float4* s;
        uint2* d;
        if (j < N_W)                    { s = (const float4*)w1; d = (uint2*)g_w1h; }
        else if ((j -= N_W) < N_W)      { s = (const float4*)w3; d = (uint2*)g_w3h; }
        else if ((j -= N_W) < N_W)      { s = (const float4*)w2; d = (uint2*)g_w2h; }
        else if ((j -= N_W) < N_A1)     { s = (const float4*)a1; d = (uint2*)g_a1h; }
        else if ((j -= N_A1) < N_A1)    { s = (const float4*)a3; d = (uint2*)g_a3h; }
        else { j -= N_A1;                 s = (const float4*)a2; d = (uint2*)g_a2h; }
        float4 v = s[j];
        uint2 o;
        o.x = packh(v.x, v.y);
        o.y = packh(v.z, v.w);
        d[j] = o;
    }
}

// ---------------- kernel: RMSNorm (+ fp16 hi/lo emit) ------------------------
__global__ void rmsnorm_kernel(const float* __restrict__ x,
                               const float* __restrict__ nw) {
    int tok = blockIdx.x;
    int tid = threadIdx.x;
    float4 v = ((const float4*)(x + (size_t)tok * DDIM))[tid];
    float ss = v.x * v.x + v.y * v.y + v.z * v.z + v.w * v.w;
#pragma unroll
    for (int o = 16; o; o >>= 1) ss += __shfl_xor_sync(0xffffffffu, ss, o);
    __shared__ float red[8];
    if ((tid & 31) == 0) red[tid >> 5] = ss;
    __syncthreads();
    float tot = 0.f;
#pragma unroll
    for (int i = 0; i < 8; ++i) tot += red[i];
    float sc = rsqrtf(tot / (float)DDIM + EPS_RMS);
    float4 w = ((const float4*)nw)[tid];
    float4 o = make_float4(v.x * sc * w.x, v.y * sc * w.y, v.z * sc * w.z,
                           v.w * sc * w.w);
    ((float4*)(g_t + (size_t)tok * DDIM))[tid] = o;
    uint2 h, l;
    split4h(o, h, l);
    ((uint2*)g_th)[tok * 256 + tid] = h;
    ((uint2*)g_tl)[tok * 256 + tid] = l;
}

// ---------------- kernel: router ---------------------------------------------
__global__ void router_kernel(const float* __restrict__ gw) {
    int tok = blockIdx.x;
    int warp = threadIdx.x >> 5, lane = threadIdx.x & 31;
    const float4* trow = (const float4*)(g_t + (size_t)tok * DDIM);
    const float4* grow = (const float4*)(gw + (size_t)warp * DDIM);
    float s = 0.f;
    for (int i = lane; i < DDIM / 4; i += 32) {
        float4 a = trow[i], b = grow[i];
        s += a.x * b.x + a.y * b.y + a.z * b.z + a.w * b.w;
    }
#pragma unroll
    for (int o = 16; o; o >>= 1) s += __shfl_xor_sync(0xffffffffu, s, o);
    __shared__ float lg[NEXP];
    if (lane == 0) lg[warp] = s;
    __syncthreads();
    if (threadIdx.x == 0) {
        int i0 = 0;
#pragma unroll
        for (int i = 1; i < NEXP; ++i) if (lg[i] > lg[i0]) i0 = i;
        int i1 = (i0 == 0) ? 1 : 0;
#pragma unroll
        for (int i = 0; i < NEXP; ++i) if (i != i0 && lg[i] > lg[i1]) i1 = i;
        float e1 = expf(lg[i1] - lg[i0]);
        float inv = 1.f / (1.f + e1);
        g_topi[tok * 2 + 0] = i0;
        g_topi[tok * 2 + 1] = i1;
        g_topw[tok * 2 + 0] = inv;
        g_topw[tok * 2 + 1] = e1 * inv;
    }
}

// ---------------- kernel: expert-sort pairs + zero etr2 ----------------------
__global__ void sort_kernel() {
    __shared__ int cnt[NEXP], ofs[NEXP + 1], cur[NEXP];
    int tid = threadIdx.x;
    for (int i = tid; i < NPAIR * RLORA; i += 256) g_etr2[i] = 0.f;
    if (tid < NEXP) cnt[tid] = 0;
    __syncthreads();
    for (int p = tid; p < NPAIR; p += 256) atomicAdd(&cnt[g_topi[p]], 1);
    __syncthreads();
    if (tid == 0) {
        ofs[0] = 0;
        for (int e = 0; e < NEXP; ++e) { ofs[e + 1] = ofs[e] + cnt[e]; cur[e] = ofs[e]; }
        int ng = 0;
        for (int e = 0; e < NEXP; ++e)
            for (int s = 0; s < cnt[e]; s += GSZ) {
                g_gstart[ng] = ofs[e] + s;
                g_glen[ng] = min(GSZ, cnt[e] - s);
                g_gexp[ng] = e;
                ng++;
            }
        g_ngroups = ng;
    }
    __syncthreads();
    for (int p = tid; p < NPAIR; p += 256) {
        int pos = atomicAdd(&cur[g_topi[p]], 1);
        g_sorted[pos] = p;
    }
}

// ---------------- kernel: up GEMMs (128x64 tile, 2-pass fp16) ----------------
#define UP_TA (128 * 64 * 2)
#define UP_TB (64 * 64 * 2)
#define UP_STAGE (2 * UP_TA + UP_TB)
__global__ __launch_bounds__(256, 2) void up_mma_kernel() {
    extern __shared__ __align__(128) char smem[];
    const int tid = threadIdx.x;
    const int wid = tid >> 5, lane = tid & 31;
    const int warpRow = (wid >> 1) * 32, warpCol = (wid & 1) * 32;
    uint32_t sb = smem_u32(smem);

    const __half* Ah = g_th + (size_t)blockIdx.y * 128 * DDIM;
    const __half* Al = g_tl + (size_t)blockIdx.y * 128 * DDIM;
    const __half* Bh = (blockIdx.z ? g_w3h : g_w1h) + (size_t)blockIdx.x * 64 * DDIM;

    float acc[2][4][4] = {};
    const int NC = DDIM / 64;

    {
        uint32_t s0 = sb;
        load_tile<128, 256>(s0, Ah, DDIM, tid);
        load_tile<128, 256>(s0 + UP_TA, Al, DDIM, tid);
        load_tile<64, 256>(s0 + 2 * UP_TA, Bh, DDIM, tid);
        cp_commit();
    }
    for (int c = 0; c < NC; ++c) {
        if (c + 1 < NC) {
            uint32_t s1 = sb + ((c + 1) & 1) * UP_STAGE;
            load_tile<128, 256>(s1, Ah + (c + 1) * 64, DDIM, tid);
            load_tile<128, 256>(s1 + UP_TA, Al + (c + 1) * 64, DDIM, tid);
            load_tile<64, 256>(s1 + 2 * UP_TA, Bh + (c + 1) * 64, DDIM, tid);
            cp_commit();
            cp_wait1();
        } else {
            cp_wait0();
        }
        __syncthreads();
        uint32_t s = sb + (c & 1) * UP_STAGE;
        compute_chunk2<2, 4>(s, s + UP_TA, s + 2 * UP_TA, warpRow, warpCol, lane, acc);
        __syncthreads();
    }

    float* dst = blockIdx.z ? g_base3 : g_base1;
    int grp = lane >> 2, q = lane & 3;
#pragma unroll
    for (int i = 0; i < 2; ++i) {
        int r0 = blockIdx.y * 128 + warpRow + i * 16 + grp;
#pragma unroll
        for (int j = 0; j < 4; ++j) {
            int col = blockIdx.x * 64 + warpCol + j * 8 + q * 2;
            *(float2*)(dst + (size_t)r0 * FDIM + col) =
                make_float2(acc[i][j][0], acc[i][j][1]);
            *(float2*)(dst + (size_t)(r0 + 8) * FDIM + col) =
                make_float2(acc[i][j][2], acc[i][j][3]);
        }
    }
}

// ---------------- kernel: up LoRA rank projections (fp16 a) ------------------
__global__ void etr_up_kernel() {
    int p = blockIdx.x, tok = p >> 1, e = g_topi[p];
    int warp = threadIdx.x >> 5, lane = threadIdx.x & 31;
    const float4* trow = (const float4*)(g_t + (size_t)tok * DDIM);
#pragma unroll
    for (int j = 0; j < 4; ++j) {
        int idx = warp * 4 + j;
        int mat = idx >> 4, r = idx & 15;
        const __half* A = mat ? g_a3h : g_a1h;
        const uint2* arow = (const uint2*)(A + ((size_t)e * RLORA + r) * DDIM);
        float s = 0.f;
        for (int i = lane; i < DDIM / 4; i += 32) {
            float4 u = trow[i];
            uint2 av = arow[i];
            float2 a01 = h22f2(av.x), a23 = h22f2(av.y);
            s += u.x * a01.x + u.y * a01.y + u.z * a23.x + u.w * a23.y;
        }
#pragma unroll
        for (int o = 16; o; o >>= 1) s += __shfl_xor_sync(0xffffffffu, s, o);
        if (lane == 0) g_etrup[p * 32 + mat * 16 + r] = s;
    }
}

// ---------------- kernel: grouped LoRA expand + SwiGLU (fp16 act) ------------
__global__ __launch_bounds__(256) void act_group_kernel(const float* __restrict__ b1w,
                                                        const float* __restrict__ b3w) {
    int gi = blockIdx.x;
    if (gi >= g_ngroups) return;
    int e = g_gexp[gi], start = g_gstart[gi], len = g_glen[gi];
    int tid = threadIdx.x;
    int f0 = blockIdx.y * 512 + tid * 2;
    __shared__ float sg[GSZ][32];
    __shared__ int sp[GSZ];
    for (int i = tid; i < len * 32; i += 256) {
        int k = i >> 5;
        sg[k][i & 31] = g_etrup[g_sorted[start + k] * 32 + (i & 31)];
    }
    if (tid < len) sp[tid] = g_sorted[start + tid];
    __syncthreads();

    float b1r[2][16], b3r[2][16];
#pragma unroll
    for (int fi = 0; fi < 2; ++fi) {
        const float4* q1 = (const float4*)(b1w + ((size_t)e * FDIM + f0 + fi) * RLORA);
        const float4* q3 = (const float4*)(b3w + ((size_t)e * FDIM + f0 + fi) * RLORA);
#pragma unroll
        for (int i = 0; i < 4; ++i) {
            float4 v1 = q1[i], v3 = q3[i];
            b1r[fi][i * 4 + 0] = v1.x; b1r[fi][i * 4 + 1] = v1.y;
            b1r[fi][i * 4 + 2] = v1.z; b1r[fi][i * 4 + 3] = v1.w;
            b3r[fi][i * 4 + 0] = v3.x; b3r[fi][i * 4 + 1] = v3.y;
            b3r[fi][i * 4 + 2] = v3.z; b3r[fi][i * 4 + 3] = v3.w;
        }
    }
    for (int k = 0; k < len; ++k) {
        int p = sp[k], tok = p >> 1;
        float2 bs1 = *(const float2*)(g_base1 + (size_t)tok * FDIM + f0);
        float2 bs3 = *(const float2*)(g_base3 + (size_t)tok * FDIM + f0);
        float hv[2];
#pragma unroll
        for (int fi = 0; fi < 2; ++fi) {
            float l1 = 0.f, l3 = 0.f;
#pragma unroll
            for (int r = 0; r < 16; ++r) {
                l1 += b1r[fi][r] * sg[k][r];
                l3 += b3r[fi][r] * sg[k][16 + r];
            }
            float h1 = (fi ? bs1.y : bs1.x) + SCALING * l1;
            float h3 = (fi ? bs3.y : bs3.x) + SCALING * l3;
            hv[fi] = (h1 / (1.f + expf(-h1))) * h3;
        }
        ((uint32_t*)g_acth)[((size_t)p * FDIM + f0) >> 1] = packh(hv[0], hv[1]);
    }
}

// ---------------- kernel: grouped down LoRA rank projection ------------------
// grid (MAXG, 4 f-chunks). smem-cached a2 chunk; atomic partial sums.
#define A2PITCH 516
__global__ __launch_bounds__(256) void etr2_group_kernel() {
    int gi = blockIdx.x;
    if (gi >= g_ngroups) return;
    int e = g_gexp[gi], start = g_gstart[gi], len = g_glen[gi];
    int cidx = blockIdx.y;
    int tid = threadIdx.x;
    extern __shared__ __align__(16) uint32_t sm[];
    uint32_t* sa2 = sm;                       // [16][A2PITCH]
    uint32_t* sact = sm + 16 * A2PITCH;       // [32][A2PITCH]
    __shared__ int sp[GSZ];
    if (tid < len) sp[tid] = g_sorted[start + tid];
    __syncthreads();
    const uint32_t* a2g = (const uint32_t*)g_a2h;
    for (int i = tid; i < 16 * 512; i += 256) {
        int r = i >> 9, d = i & 511;
        sa2[r * A2PITCH + d] = a2g[((size_t)(e * RLORA + r) << 11) + (cidx << 9) + d];
    }
    const uint32_t* actg = (const uint32_t*)g_acth;
    for (int i = tid; i < len * 512; i += 256) {
        int k = i >> 9, d = i & 511;
        sact[k * A2PITCH + d] = actg[((size_t)sp[k] << 11) + (cidx << 9) + d];
    }
    __syncthreads();
    int k = tid >> 3, rr = tid & 7;
    if (k < len) {
        float a0 = 0.f, a1 = 0.f;
        const uint32_t* ar = sact + k * A2PITCH;
        const uint32_t* b0 = sa2 + rr * A2PITCH;
        const uint32_t* b1 = sa2 + (rr + 8) * A2PITCH;
#pragma unroll 4
        for (int d = 0; d < 512; ++d) {
            float2 av = h22f2(ar[d]);
            float2 v0 = h22f2(b0[d]);
            float2 v1 = h22f2(b1[d]);
            a0 += av.x * v0.x + av.y * v0.y;
            a1 += av.x * v1.x + av.y * v1.y;
        }
        int p = sp[k];
        float sc = SCALING * g_topw[p];
        atomicAdd(&g_etr2[p * RLORA + rr], a0 * sc);
        atomicAdd(&g_etr2[p * RLORA + rr + 8], a1 * sc);
    }
}

// ---------------- kernel: weighted pair combine (fp16 -> hi/lo split) --------
__global__ void combine_kernel() {
    int tok = blockIdx.x;
    int f0 = (blockIdx.y * 256 + threadIdx.x) * 4;
    float w0 = g_topw[tok * 2], w1 = g_topw[tok * 2 + 1];
    size_t i0 = ((size_t)(2 * tok) * FDIM + f0) >> 2;
    size_t i1 = i0 + (FDIM >> 2);
    uint2 u0 = ((const uint2*)g_acth)[i0];
    uint2 u1 = ((const uint2*)g_acth)[i1];
    float2 a01 = h22f2(u0.x), a23 = h22f2(u0.y);
    float2 b01 = h22f2(u1.x), b23 = h22f2(u1.y);
    float4 c = make_float4(w0 * a01.x + w1 * b01.x, w0 * a01.y + w1 * b01.y,
                           w0 * a23.x + w1 * b23.x, w0 * a23.y + w1 * b23.y);
    uint2 h, l;
    split4h(c, h, l);
    size_t o = ((size_t)tok * FDIM + f0) >> 2;
    ((uint2*)g_ch)[o] = h;
    ((uint2*)g_cl)[o] = l;
}

// ---------------- kernel: down GEMM (64x64, 2-pass) + LoRA epilogue ----------
#define DN_T (64 * 64 * 2)
#define DN_STAGE (3 * DN_T)
__global__ __launch_bounds__(256, 2) void down_mma_kernel(const float* __restrict__ B2,
                                                          float* __restrict__ Out) {
    extern __shared__ __align__(128) char smem[];
    const int tid = threadIdx.x;
    const int wid = tid >> 5, lane = tid & 31;
    const int warpRow = (wid >> 2) * 32, warpCol = (wid & 3) * 16;
    uint32_t sb = smem_u32(smem);

    const __half* Ah = g_ch + (size_t)blockIdx.y * 64 * FDIM;
    const __half* Al = g_cl + (size_t)blockIdx.y * 64 * FDIM;
    const __half* Bh = g_w2h + (size_t)blockIdx.x * 64 * FDIM;

    float acc[2][2][4] = {};
    const int NC = FDIM / 64;

    {
        uint32_t s0 = sb;
        load_tile<64, 256>(s0, Ah, FDIM, tid);
        load_tile<64, 256>(s0 + DN_T, Al, FDIM, tid);
        load_tile<64, 256>(s0 + 2 * DN_T, Bh, FDIM, tid);
        cp_commit();
    }
    for (int c = 0; c < NC; ++c) {
        if (c + 1 < NC) {
            uint32_t s1 = sb + ((c + 1) & 1) * DN_STAGE;
            load_tile<64, 256>(s1, Ah + (c + 1) * 64, FDIM, tid);
            load_tile<64, 256>(s1 + DN_T, Al + (c + 1) * 64, FDIM, tid);
            load_tile<64, 256>(s1 + 2 * DN_T, Bh + (c + 1) * 64, FDIM, tid);
            cp_commit();
            cp_wait1();
        } else {
            cp_wait0();
        }
        __syncthreads();
        uint32_t s = sb + (c & 1) * DN_STAGE;
        compute_chunk2<2, 2>(s, s + DN_T, s + 2 * DN_T, warpRow, warpCol, lane, acc);
        __syncthreads();
    }

    int grp = lane >> 2, q = lane & 3;
#pragma unroll
    for (int i = 0; i < 2; ++i) {
#pragma unroll
        for (int half = 0; half < 2; ++half) {
            int t = blockIdx.y * 64 + warpRow + i * 16 + half * 8 + grp;
            int p0 = 2 * t, p1 = 2 * t + 1;
            int e0 = g_topi[p0], e1 = g_topi[p1];
            float er0[16], er1[16];
            {
                const float4* q0 = (const float4*)(g_etr2 + p0 * RLORA);
                const float4* q1v = (const float4*)(g_etr2 + p1 * RLORA);
#pragma unroll
                for (int kk = 0; kk < 4; ++kk) {
                    float4 a = q0[kk], b = q1v[kk];
                    er0[kk * 4 + 0] = a.x; er0[kk * 4 + 1] = a.y;
                    er0[kk * 4 + 2] = a.z; er0[kk * 4 + 3] = a.w;
                    er1[kk * 4 + 0] = b.x; er1[kk * 4 + 1] = b.y;
                    er1[kk * 4 + 2] = b.z; er1[kk * 4 + 3] = b.w;
                }
            }
#pragma unroll
            for (int j = 0; j < 2; ++j) {
                int d0 = blockIdx.x * 64 + warpCol + j * 8 + q * 2;
                float ov[2];
#pragma unroll
                for (int c2 = 0; c2 < 2; ++c2) {
                    int d = d0 + c2;
                    const float4* r0p = (const float4*)(B2 + ((size_t)e0 * DDIM + d) * RLORA);
                    const float4* r1p = (const float4*)(B2 + ((size_t)e1 * DDIM + d) * RLORA);
                    float dot = 0.f;
#pragma unroll
                    for (int kk = 0; kk < 4; ++kk) {
                        float4 b0 = r0p[kk], b1v = r1p[kk];
                        dot += b0.x * er0[kk * 4 + 0] + b0.y * er0[kk * 4 + 1] +
                               b0.z * er0[kk * 4 + 2] + b0.w * er0[kk * 4 + 3];
                        dot += b1v.x * er1[kk * 4 + 0] + b1v.y * er1[kk * 4 + 1] +
                               b1v.z * er1[kk * 4 + 2] + b1v.w * er1[kk * 4 + 3];
                    }
                    ov[c2] = acc[i][j][half * 2 + c2] + dot;
                }
                *(float2*)(Out + (size_t)t * DDIM + d0) = make_float2(ov[0], ov[1]);
            }
        }
    }
}

// ---------------- launcher ---------------------------------------------------
extern "C" void kernel_launch(void* const* d_in, const int* in_sizes, int n_in,
                              void* d_out, int out_size) {
    const float* x      = (const float*)d_in[0];
    const float* norm_w = (const float*)d_in[1];
    const float* w1     = (const float*)d_in[2];
    const float* w3     = (const float*)d_in[3];
    const float* w2     = (const float*)d_in[4];
    const float* gate_w = (const float*)d_in[5];
    const float* a1     = (const float*)d_in[6];
    const float* b1     = (const float*)d_in[7];
    const float* a3     = (const float*)d_in[8];
    const float* b3     = (const float*)d_in[9];
    const float* a2     = (const float*)d_in[10];
    const float* b2     = (const float*)d_in[11];
    float* out = (float*)d_out;

    const int ETR2_SMEM = (16 + 32) * A2PITCH * 4;  // 99072
    cudaFuncSetAttribute(up_mma_kernel,
                         cudaFuncAttributeMaxDynamicSharedMemorySize, 2 * UP_STAGE);
    cudaFuncSetAttribute(down_mma_kernel,
                         cudaFuncAttributeMaxDynamicSharedMemorySize, 2 * DN_STAGE);
    cudaFuncSetAttribute(etr2_group_kernel,
                         cudaFuncAttributeMaxDynamicSharedMemorySize, ETR2_SMEM);

    cvt_kernel<<<1024, 256>>>(w1, w3, w2, a1, a3, a2);
    rmsnorm_kernel<<<T_TOK, 256>>>(x, norm_w);
    router_kernel<<<T_TOK, 256>>>(gate_w);
    sort_kernel<<<1, 256>>>();
    up_mma_kernel<<<dim3(FDIM / 64, T_TOK / 128, 2), 256, 2 * UP_STAGE>>>();
    etr_up_kernel<<<NPAIR, 256>>>();
    act_group_kernel<<<dim3(MAXG, 8), 256>>>(b1, b3);
    etr2_group_kernel<<<dim3(MAXG, 4), 256, ETR2_SMEM>>>();
    combine_kernel<<<dim3(T_TOK, 4), 256>>>();
    down_mma_kernel<<<dim3(DDIM / 64, T_TOK / 64), 256, 2 * DN_STAGE>>>(b2, out);
}

// round 6
// speedup vs baseline: 4.0823x; 1.0075x over previous
#include <cuda_runtime.h>
#include <cuda_fp16.h>
#include <cstdint>
#include <math.h>

// Problem dims
#define T_TOK 512
#define DDIM 1024
#define FDIM 4096
#define NEXP 8
#define RLORA 16
#define NPAIR 1024
#define SCALING 2.0f
#define EPS_RMS 1e-6f
#define GSZ 32
#define MAXG 40

// ---------------- scratch (device globals) ----------------------------------
__device__ float g_t[T_TOK * DDIM];
__device__ __half g_th[T_TOK * DDIM], g_tl[T_TOK * DDIM];
__device__ __half g_w1h[FDIM * DDIM], g_w3h[FDIM * DDIM];
__device__ __half g_w2h[DDIM * FDIM];
__device__ __half g_a1h[NEXP * RLORA * DDIM], g_a3h[NEXP * RLORA * DDIM];
__device__ __half g_a2h[NEXP * RLORA * FDIM];
__device__ __half g_acth[NPAIR * FDIM];
__device__ __half g_ch[T_TOK * FDIM], g_cl[T_TOK * FDIM];
__device__ float g_base1[T_TOK * FDIM];
__device__ float g_base3[T_TOK * FDIM];
__device__ float g_etrup[NPAIR * 2 * RLORA];
__device__ float g_etr2[NPAIR * RLORA];
__device__ int   g_topi[NPAIR];
__device__ float g_topw[NPAIR];
__device__ int   g_sorted[NPAIR];
__device__ int   g_gstart[MAXG], g_glen[MAXG], g_gexp[MAXG];
__device__ int   g_ngroups;

// ---------------- helpers ----------------------------------------------------
__device__ __forceinline__ uint32_t smem_u32(const void* p) {
    return (uint32_t)__cvta_generic_to_shared(p);
}
__device__ __forceinline__ uint32_t packh(float a, float b) {
    return ((uint32_t)__half_as_ushort(__float2half_rn(b)) << 16) |
           __half_as_ushort(__float2half_rn(a));
}
__device__ __forceinline__ void split4h(float4 v, uint2& h, uint2& l) {
    __half hx = __float2half_rn(v.x), hy = __float2half_rn(v.y);
    __half hz = __float2half_rn(v.z), hw = __float2half_rn(v.w);
    h.x = ((uint32_t)__half_as_ushort(hy) << 16) | __half_as_ushort(hx);
    h.y = ((uint32_t)__half_as_ushort(hw) << 16) | __half_as_ushort(hz);
    l.x = packh(v.x - __half2float(hx), v.y - __half2float(hy));
    l.y = packh(v.z - __half2float(hz), v.w - __half2float(hw));
}
__device__ __forceinline__ float2 h22f2(uint32_t u) {
    return __half22float2(*(__half2*)&u);
}

__device__ __forceinline__ void ldsm_x4(uint32_t (&r)[4], uint32_t a) {
    asm volatile("ldmatrix.sync.aligned.m8n8.x4.shared.b16 {%0,%1,%2,%3}, [%4];"
                 : "=r"(r[0]), "=r"(r[1]), "=r"(r[2]), "=r"(r[3]) : "r"(a));
}
__device__ __forceinline__ void ldsm_x2(uint32_t (&r)[2], uint32_t a) {
    asm volatile("ldmatrix.sync.aligned.m8n8.x2.shared.b16 {%0,%1}, [%2];"
                 : "=r"(r[0]), "=r"(r[1]) : "r"(a));
}
__device__ __forceinline__ void mma_f16(float (&c)[4], const uint32_t (&a)[4],
                                        const uint32_t (&b)[2]) {
    asm volatile(
        "mma.sync.aligned.m16n8k16.row.col.f32.f16.f16.f32 "
        "{%0,%1,%2,%3}, {%4,%5,%6,%7}, {%8,%9}, {%0,%1,%2,%3};"
        : "+f"(c[0]), "+f"(c[1]), "+f"(c[2]), "+f"(c[3])
        : "r"(a[0]), "r"(a[1]), "r"(a[2]), "r"(a[3]), "r"(b[0]), "r"(b[1]));
}
__device__ __forceinline__ void cp16(uint32_t dst, const void* src) {
    asm volatile("cp.async.cg.shared.global [%0], [%1], 16;" :: "r"(dst), "l"(src));
}
__device__ __forceinline__ void cp_commit() {
    asm volatile("cp.async.commit_group;" ::: "memory");
}
__device__ __forceinline__ void cp_wait1() {
    asm volatile("cp.async.wait_group 1;" ::: "memory");
}
__device__ __forceinline__ void cp_wait0() {
    asm volatile("cp.async.wait_group 0;" ::: "memory");
}

// load ROWS x 64 fp16 tile into SW128-swizzled smem via cp.async
template <int ROWS, int THREADS>
__device__ __forceinline__ void load_tile(uint32_t sdst, const __half* g,
                                          int ld, int tid) {
#pragma unroll
    for (int i = 0; i < ROWS * 8 / THREADS; ++i) {
        int idx = i * THREADS + tid;
        int row = idx >> 3, ch = idx & 7;
        uint32_t dst = sdst + row * 128 + ((ch * 16) ^ ((row & 7) << 4));
        cp16(dst, g + (size_t)row * ld + ch * 8);
    }
}

// one K-chunk (64) of 2-pass mma: acc += Ah*Bh + Al*Bh  (A-quantization cancels)
template <int MT, int NT>
__device__ __forceinline__ void compute_chunk2(uint32_t sAh, uint32_t sAl,
                                               uint32_t sBh,
                                               int warpRow, int warpCol, int lane,
                                               float (&acc)[MT][NT][4]) {
    int mi = lane >> 3;
    int arow = warpRow + ((mi & 1) << 3) + (lane & 7);
    uint32_t axor = (uint32_t)((arow & 7) << 4);
    uint32_t aoff = (uint32_t)arow * 128;
    int akb = (mi >> 1) << 4;
    int brow = warpCol + (lane & 7);
    int bi = (lane >> 3) & 1;
    uint32_t bxor = (uint32_t)((brow & 7) << 4);
    uint32_t boff = (uint32_t)brow * 128;
    int bkb = bi << 4;
#pragma unroll
    for (int ks = 0; ks < 4; ++ks) {
        uint32_t af[MT][4], bh[NT][2];
        uint32_t ak = (uint32_t)((ks * 32 + akb) ^ axor);
        uint32_t bk = (uint32_t)((ks * 32 + bkb) ^ bxor);
#pragma unroll
        for (int i = 0; i < MT; ++i) ldsm_x4(af[i], sAh + aoff + i * 2048 + ak);
#pragma unroll
        for (int j = 0; j < NT; ++j) ldsm_x2(bh[j], sBh + boff + j * 1024 + bk);
#pragma unroll
        for (int i = 0; i < MT; ++i)
#pragma unroll
            for (int j = 0; j < NT; ++j) mma_f16(acc[i][j], af[i], bh[j]);
#pragma unroll
        for (int i = 0; i < MT; ++i) ldsm_x4(af[i], sAl + aoff + i * 2048 + ak);
#pragma unroll
        for (int i = 0; i < MT; ++i)
#pragma unroll
            for (int j = 0; j < NT; ++j) mma_f16(acc[i][j], af[i], bh[j]);
    }
}

// ---------------- kernel: fp32 -> fp16 conversions (all weights) -------------
#define N_W (FDIM * DDIM / 4)
#define N_A1 (NEXP * RLORA * DDIM / 4)
#define N_A2 (NEXP * RLORA * FDIM / 4)
__global__ void cvt_kernel(const float* __restrict__ w1, const float* __restrict__ w3,
                           const float* __restrict__ w2, const float* __restrict__ a1,
                           const float* __restrict__ a3, const float* __restrict__ a2) {
    const int total = 3 * N_W + 2 * N_A1 + N_A2;
    for (int i = blockIdx.x * blockDim.x + threadIdx.x; i < total;
         i += gridDim.x * blockDim.x) {
        int j = i;
        const float4* s;
        uint2* d;
        if (j < N_W)                    { s = (const float4*)w1; d = (uint2*)g_w1h; }
        else if ((j -= N_W) < N_W)      { s = (const float4*)w3; d = (uint2*)g_w3h; }
        else if ((j -= N_W) < N_W)      { s = (const float4*)w2; d = (uint2*)g_w2h; }
        else if ((j -= N_W) < N_A1)     { s = (const float4*)a1; d = (uint2*)g_a1h; }
        else if ((j -= N_A1) < N_A1)    { s = (const float4*)a3; d = (uint2*)g_a3h; }
        else { j -= N_A1;                 s = (const float4*)a2; d = (uint2*)g_a2h; }
        float4 v = s[j];
        uint2 o;
        o.x = packh(v.x, v.y);
        o.y = packh(v.z, v.w);
        d[j] = o;
    }
}

// ---------------- kernel: fused RMSNorm + router (+ etr2 zero) ---------------
__global__ void rmsnorm_router_kernel(const float* __restrict__ x,
                                      const float* __restrict__ nw,
                                      const float* __restrict__ gw) {
    int tok = blockIdx.x;
    int tid = threadIdx.x;
    // parallel zero of g_etr2 (NPAIR*RLORA = T_TOK*32)
    if (tid < 32) g_etr2[tok * 32 + tid] = 0.f;
    float4 v = ((const float4*)(x + (size_t)tok * DDIM))[tid];
    float ss = v.x * v.x + v.y * v.y + v.z * v.z + v.w * v.w;
#pragma unroll
    for (int o = 16; o; o >>= 1) ss += __shfl_xor_sync(0xffffffffu, ss, o);
    __shared__ float red[8];
    if ((tid & 31) == 0) red[tid >> 5] = ss;
    __syncthreads();
    float tot = 0.f;
#pragma unroll
    for (int i = 0; i < 8; ++i) tot += red[i];
    float sc = rsqrtf(tot / (float)DDIM + EPS_RMS);
    float4 w = ((const float4*)nw)[tid];
    float4 o = make_float4(v.x * sc * w.x, v.y * sc * w.y, v.z * sc * w.z,
                           v.w * sc * w.w);
    ((float4*)(g_t + (size_t)tok * DDIM))[tid] = o;
    uint2 h, l;
    split4h(o, h, l);
    ((uint2*)g_th)[tok * 256 + tid] = h;
    ((uint2*)g_tl)[tok * 256 + tid] = l;

    // router: 8 expert dots from the already-registered t chunk
    float r[NEXP];
#pragma unroll
    for (int e = 0; e < NEXP; ++e) {
        float4 gv = ((const float4*)gw)[e * 256 + tid];
        r[e] = o.x * gv.x + o.y * gv.y + o.z * gv.z + o.w * gv.w;
    }
#pragma unroll
    for (int e = 0; e < NEXP; ++e) {
#pragma unroll
        for (int off = 16; off; off >>= 1)
            r[e] += __shfl_xor_sync(0xffffffffu, r[e], off);
    }
    __shared__ float lg[8][NEXP];
    if ((tid & 31) == 0) {
#pragma unroll
        for (int e = 0; e < NEXP; ++e) lg[tid >> 5][e] = r[e];
    }
    __syncthreads();
    if (tid == 0) {
        float s8[NEXP];
#pragma unroll
        for (int e = 0; e < NEXP; ++e) {
            float t = 0.f;
#pragma unroll
            for (int wgi = 0; wgi < 8; ++wgi) t += lg[wgi][e];
            s8[e] = t;
        }
        int i0 = 0;
#pragma unroll
        for (int i = 1; i < NEXP; ++i) if (s8[i] > s8[i0]) i0 = i;
        int i1 = (i0 == 0) ? 1 : 0;
#pragma unroll
        for (int i = 0; i < NEXP; ++i) if (i != i0 && s8[i] > s8[i1]) i1 = i;
        float e1 = expf(s8[i1] - s8[i0]);
        float inv = 1.f / (1.f + e1);
        g_topi[tok * 2 + 0] = i0;
        g_topi[tok * 2 + 1] = i1;
        g_topw[tok * 2 + 0] = inv;
        g_topw[tok * 2 + 1] = e1 * inv;
    }
}

// ---------------- kernel: expert-sort pairs ----------------------------------
__global__ void sort_kernel() {
    __shared__ int cnt[NEXP], ofs[NEXP + 1], cur[NEXP];
    int tid = threadIdx.x;
    if (tid < NEXP) cnt[tid] = 0;
    __syncthreads();
    for (int p = tid; p < NPAIR; p += 256) atomicAdd(&cnt[g_topi[p]], 1);
    __syncthreads();
    if (tid == 0) {
        ofs[0] = 0;
        for (int e = 0; e < NEXP; ++e) { ofs[e + 1] = ofs[e] + cnt[e]; cur[e] = ofs[e]; }
        int ng = 0;
        for (int e = 0; e < NEXP; ++e)
            for (int s = 0; s < cnt[e]; s += GSZ) {
                g_gstart[ng] = ofs[e] + s;
                g_glen[ng] = min(GSZ, cnt[e] - s);
                g_gexp[ng] = e;
                ng++;
            }
        g_ngroups = ng;
    }
    __syncthreads();
    for (int p = tid; p < NPAIR; p += 256) {
        int pos = atomicAdd(&cur[g_topi[p]], 1);
        g_sorted[pos] = p;
    }
}

// ---------------- kernel: up GEMMs (128x128 tile, 2-pass fp16) ---------------
#define UP_TA (128 * 64 * 2)
#define UP_TB (128 * 64 * 2)
#define UP_STAGE (2 * UP_TA + UP_TB)
__global__ __launch_bounds__(256, 2) void up_mma_kernel() {
    extern __shared__ __align__(128) char smem[];
    const int tid = threadIdx.x;
    const int wid = tid >> 5, lane = tid & 31;
    const int warpRow = (wid >> 1) * 32, warpCol = (wid & 1) * 64;
    uint32_t sb = smem_u32(smem);

    const __half* Ah = g_th + (size_t)blockIdx.y * 128 * DDIM;
    const __half* Al = g_tl + (size_t)blockIdx.y * 128 * DDIM;
    const __half* Bh = (blockIdx.z ? g_w3h : g_w1h) + (size_t)blockIdx.x * 128 * DDIM;

    float acc[2][8][4] = {};
    const int NC = DDIM / 64;

    {
        uint32_t s0 = sb;
        load_tile<128, 256>(s0, Ah, DDIM, tid);
        load_tile<128, 256>(s0 + UP_TA, Al, DDIM, tid);
        load_tile<128, 256>(s0 + 2 * UP_TA, Bh, DDIM, tid);
        cp_commit();
    }
    for (int c = 0; c < NC; ++c) {
        if (c + 1 < NC) {
            uint32_t s1 = sb + ((c + 1) & 1) * UP_STAGE;
            load_tile<128, 256>(s1, Ah + (c + 1) * 64, DDIM, tid);
            load_tile<128, 256>(s1 + UP_TA, Al + (c + 1) * 64, DDIM, tid);
            load_tile<128, 256>(s1 + 2 * UP_TA, Bh + (c + 1) * 64, DDIM, tid);
            cp_commit();
            cp_wait1();
        } else {
            cp_wait0();
        }
        __syncthreads();
        uint32_t s = sb + (c & 1) * UP_STAGE;
        compute_chunk2<2, 8>(s, s + UP_TA, s + 2 * UP_TA, warpRow, warpCol, lane, acc);
        __syncthreads();
    }

    float* dst = blockIdx.z ? g_base3 : g_base1;
    int grp = lane >> 2, q = lane & 3;
#pragma unroll
    for (int i = 0; i < 2; ++i) {
        int r0 = blockIdx.y * 128 + warpRow + i * 16 + grp;
#pragma unroll
        for (int j = 0; j < 8; ++j) {
            int col = blockIdx.x * 128 + warpCol + j * 8 + q * 2;
            *(float2*)(dst + (size_t)r0 * FDIM + col) =
                make_float2(acc[i][j][0], acc[i][j][1]);
            *(float2*)(dst + (size_t)(r0 + 8) * FDIM + col) =
                make_float2(acc[i][j][2], acc[i][j][3]);
        }
    }
}

// ---------------- kernel: up LoRA rank projections (fp16 a) ------------------
__global__ void etr_up_kernel() {
    int p = blockIdx.x, tok = p >> 1, e = g_topi[p];
    int warp = threadIdx.x >> 5, lane = threadIdx.x & 31;
    const float4* trow = (const float4*)(g_t + (size_t)tok * DDIM);
#pragma unroll
    for (int j = 0; j < 4; ++j) {
        int idx = warp * 4 + j;
        int mat = idx >> 4, r = idx & 15;
        const __half* A = mat ? g_a3h : g_a1h;
        const uint2* arow = (const uint2*)(A + ((size_t)e * RLORA + r) * DDIM);
        float s = 0.f;
        for (int i = lane; i < DDIM / 4; i += 32) {
            float4 u = trow[i];
            uint2 av = arow[i];
            float2 a01 = h22f2(av.x), a23 = h22f2(av.y);
            s += u.x * a01.x + u.y * a01.y + u.z * a23.x + u.w * a23.y;
        }
#pragma unroll
        for (int o = 16; o; o >>= 1) s += __shfl_xor_sync(0xffffffffu, s, o);
        if (lane == 0) g_etrup[p * 32 + mat * 16 + r] = s;
    }
}

// ---------------- kernel: grouped LoRA expand + SwiGLU (fp16 act) ------------
__global__ __launch_bounds__(256) void act_group_kernel(const float* __restrict__ b1w,
                                                        const float* __restrict__ b3w) {
    int gi = blockIdx.x;
    if (gi >= g_ngroups) return;
    int e = g_gexp[gi], start = g_gstart[gi], len = g_glen[gi];
    int tid = threadIdx.x;
    int f0 = blockIdx.y * 512 + tid * 2;
    __shared__ float sg[GSZ][32];
    __shared__ int sp[GSZ];
    for (int i = tid; i < len * 32; i += 256) {
        int k = i >> 5;
        sg[k][i & 31] = g_etrup[g_sorted[start + k] * 32 + (i & 31)];
    }
    if (tid < len) sp[tid] = g_sorted[start + tid];
    __syncthreads();

    float b1r[2][16], b3r[2][16];
#pragma unroll
    for (int fi = 0; fi < 2; ++fi) {
        const float4* q1 = (const float4*)(b1w + ((size_t)e * FDIM + f0 + fi) * RLORA);
        const float4* q3 = (const float4*)(b3w + ((size_t)e * FDIM + f0 + fi) * RLORA);
#pragma unroll
        for (int i = 0; i < 4; ++i) {
            float4 v1 = q1[i], v3 = q3[i];
            b1r[fi][i * 4 + 0] = v1.x; b1r[fi][i * 4 + 1] = v1.y;
            b1r[fi][i * 4 + 2] = v1.z; b1r[fi][i * 4 + 3] = v1.w;
            b3r[fi][i * 4 + 0] = v3.x; b3r[fi][i * 4 + 1] = v3.y;
            b3r[fi][i * 4 + 2] = v3.z; b3r[fi][i * 4 + 3] = v3.w;
        }
    }
    for (int k = 0; k < len; ++k) {
        int p = sp[k], tok = p >> 1;
        float2 bs1 = *(const float2*)(g_base1 + (size_t)tok * FDIM + f0);
        float2 bs3 = *(const float2*)(g_base3 + (size_t)tok * FDIM + f0);
        float hv[2];
#pragma unroll
        for (int fi = 0; fi < 2; ++fi) {
            float l1 = 0.f, l3 = 0.f;
#pragma unroll
            for (int r = 0; r < 16; ++r) {
                l1 += b1r[fi][r] * sg[k][r];
                l3 += b3r[fi][r] * sg[k][16 + r];
            }
            float h1 = (fi ? bs1.y : bs1.x) + SCALING * l1;
            float h3 = (fi ? bs3.y : bs3.x) + SCALING * l3;
            hv[fi] = (h1 / (1.f + expf(-h1))) * h3;
        }
        ((uint32_t*)g_acth)[((size_t)p * FDIM + f0) >> 1] = packh(hv[0], hv[1]);
    }
}

// ---------------- kernel: grouped down LoRA rank projection ------------------
#define A2PITCH 516
__global__ __launch_bounds__(256) void etr2_group_kernel() {
    int gi = blockIdx.x;
    if (gi >= g_ngroups) return;
    int e = g_gexp[gi], start = g_gstart[gi], len = g_glen[gi];
    int cidx = blockIdx.y;
    int tid = threadIdx.x;
    extern __shared__ __align__(16) uint32_t sm[];
    uint32_t* sa2 = sm;                       // [16][A2PITCH]
    uint32_t* sact = sm + 16 * A2PITCH;       // [32][A2PITCH]
    __shared__ int sp[GSZ];
    if (tid < len) sp[tid] = g_sorted[start + tid];
    __syncthreads();
    const uint32_t* a2g = (const uint32_t*)g_a2h;
    for (int i = tid; i < 16 * 512; i += 256) {
        int r = i >> 9, d = i & 511;
        sa2[r * A2PITCH + d] = a2g[((size_t)(e * RLORA + r) << 11) + (cidx << 9) + d];
    }
    const uint32_t* actg = (const uint32_t*)g_acth;
    for (int i = tid; i < len * 512; i += 256) {
        int k = i >> 9, d = i & 511;
        sact[k * A2PITCH + d] = actg[((size_t)sp[k] << 11) + (cidx << 9) + d];
    }
    __syncthreads();
    int k = tid >> 3, rr = tid & 7;
    if (k < len) {
        float a0 = 0.f, a1 = 0.f;
        const uint32_t* ar = sact + k * A2PITCH;
        const uint32_t* b0 = sa2 + rr * A2PITCH;
        const uint32_t* b1 = sa2 + (rr + 8) * A2PITCH;
#pragma unroll 4
        for (int d = 0; d < 512; ++d) {
            float2 av = h22f2(ar[d]);
            float2 v0 = h22f2(b0[d]);
            float2 v1 = h22f2(b1[d]);
            a0 += av.x * v0.x + av.y * v0.y;
            a1 += av.x * v1.x + av.y * v1.y;
        }
        int p = sp[k];
        float sc = SCALING * g_topw[p];
        atomicAdd(&g_etr2[p * RLORA + rr], a0 * sc);
        atomicAdd(&g_etr2[p * RLORA + rr + 8], a1 * sc);
    }
}

// ---------------- kernel: weighted pair combine (fp16 -> hi/lo split) --------
__global__ void combine_kernel() {
    int tok = blockIdx.x;
    int f0 = (blockIdx.y * 256 + threadIdx.x) * 4;
    float w0 = g_topw[tok * 2], w1 = g_topw[tok * 2 + 1];
    size_t i0 = ((size_t)(2 * tok) * FDIM + f0) >> 2;
    size_t i1 = i0 + (FDIM >> 2);
    uint2 u0 = ((const uint2*)g_acth)[i0];
    uint2 u1 = ((const uint2*)g_acth)[i1];
    float2 a01 = h22f2(u0.x), a23 = h22f2(u0.y);
    float2 b01 = h22f2(u1.x), b23 = h22f2(u1.y);
    float4 c = make_float4(w0 * a01.x + w1 * b01.x, w0 * a01.y + w1 * b01.y,
                           w0 * a23.x + w1 * b23.x, w0 * a23.y + w1 * b23.y);
    uint2 h, l;
    split4h(c, h, l);
    size_t o = ((size_t)tok * FDIM + f0) >> 2;
    ((uint2*)g_ch)[o] = h;
    ((uint2*)g_cl)[o] = l;
}

// ---------------- kernel: down GEMM (64x128, splitK=2) + LoRA epilogue -------
#define DN_TA (64 * 64 * 2)
#define DN_TB (128 * 64 * 2)
#define DN_STAGE (2 * DN_TA + DN_TB)
__global__ __launch_bounds__(256, 2) void down_mma_kernel(const float* __restrict__ B2,
                                                          float* __restrict__ Out) {
    extern __shared__ __align__(128) char smem[];
    const int tid = threadIdx.x;
    const int wid = tid >> 5, lane = tid & 31;
    const int warpRow = (wid >> 2) * 32, warpCol = (wid & 3) * 32;
    uint32_t sb = smem_u32(smem);
    const int kOff = blockIdx.z * (FDIM / 2);

    const __half* Ah = g_ch + (size_t)blockIdx.y * 64 * FDIM + kOff;
    const __half* Al = g_cl + (size_t)blockIdx.y * 64 * FDIM + kOff;
    const __half* Bh = g_w2h + (size_t)blockIdx.x * 128 * FDIM + kOff;

    float acc[2][4][4] = {};
    const int NC = (FDIM / 2) / 64;  // 32

    {
        uint32_t s0 = sb;
        load_tile<64, 256>(s0, Ah, FDIM, tid);
        load_tile<64, 256>(s0 + DN_TA, Al, FDIM, tid);
        load_tile<128, 256>(s0 + 2 * DN_TA, Bh, FDIM, tid);
        cp_commit();
    }
    for (int c = 0; c < NC; ++c) {
        if (c + 1 < NC) {
            uint32_t s1 = sb + ((c + 1) & 1) * DN_STAGE;
            load_tile<64, 256>(s1, Ah + (c + 1) * 64, FDIM, tid);
            load_tile<64, 256>(s1 + DN_TA, Al + (c + 1) * 64, FDIM, tid);
            load_tile<128, 256>(s1 + 2 * DN_TA, Bh + (c + 1) * 64, FDIM, tid);
            cp_commit();
            cp_wait1();
        } else {
            cp_wait0();
        }
        __syncthreads();
        uint32_t s = sb + (c & 1) * DN_STAGE;
        compute_chunk2<2, 4>(s, s + DN_TA, s + 2 * DN_TA, warpRow, warpCol, lane, acc);
        __syncthreads();
    }

    int grp = lane >> 2, q = lane & 3;
#pragma unroll
    for (int i = 0; i < 2; ++i) {
#pragma unroll
        for (int half = 0; half < 2; ++half) {
            int t = blockIdx.y * 64 + warpRow + i * 16 + half * 8 + grp;
            if (blockIdx.z == 0) {
                int p0 = 2 * t, p1 = 2 * t + 1;
                int e0 = g_topi[p0], e1 = g_topi[p1];
                float er0[16], er1[16];
                const float4* q0 = (const float4*)(g_etr2 + p0 * RLORA);
                const float4* q1v = (const float4*)(g_etr2 + p1 * RLORA);
#pragma unroll
                for (int kk = 0; kk < 4; ++kk) {
                    float4 a = q0[kk], b = q1v[kk];
                    er0[kk * 4 + 0] = a.x; er0[kk * 4 + 1] = a.y;
                    er0[kk * 4 + 2] = a.z; er0[kk * 4 + 3] = a.w;
                    er1[kk * 4 + 0] = b.x; er1[kk * 4 + 1] = b.y;
                    er1[kk * 4 + 2] = b.z; er1[kk * 4 + 3] = b.w;
                }
#pragma unroll
                for (int j = 0; j < 4; ++j) {
#pragma unroll
                    for (int c2 = 0; c2 < 2; ++c2) {
                        int d = blockIdx.x * 128 + warpCol + j * 8 + q * 2 + c2;
                        const float4* r0p =
                            (const float4*)(B2 + ((size_t)e0 * DDIM + d) * RLORA);
                        const float4* r1p =
                            (const float4*)(B2 + ((size_t)e1 * DDIM + d) * RLORA);
                        float dot = 0.f;
#pragma unroll
                        for (int kk = 0; kk < 4; ++kk) {
                            float4 b0 = r0p[kk], b1v = r1p[kk];
                            dot += b0.x * er0[kk * 4 + 0] + b0.y * er0[kk * 4 + 1] +
                                   b0.z * er0[kk * 4 + 2] + b0.w * er0[kk * 4 + 3];
                            dot += b1v.x * er1[kk * 4 + 0] + b1v.y * er1[kk * 4 + 1] +
                                   b1v.z * er1[kk * 4 + 2] + b1v.w * er1[kk * 4 + 3];
                        }
                        atomicAdd(&Out[(size_t)t * DDIM + d],
                                  acc[i][j][half * 2 + c2] + dot);
                    }
                }
            } else {
#pragma unroll
                for (int j = 0; j < 4; ++j) {
#pragma unroll
                    for (int c2 = 0; c2 < 2; ++c2) {
                        int d = blockIdx.x * 128 + warpCol + j * 8 + q * 2 + c2;
                        atomicAdd(&Out[(size_t)t * DDIM + d], acc[i][j][half * 2 + c2]);
                    }
                }
            }
        }
    }
}

// ---------------- launcher ---------------------------------------------------
extern "C" void kernel_launch(void* const* d_in, const int* in_sizes, int n_in,
                              void* d_out, int out_size) {
    const float* x      = (const float*)d_in[0];
    const float* norm_w = (const float*)d_in[1];
    const float* w1     = (const float*)d_in[2];
    const float* w3     = (const float*)d_in[3];
    const float* w2     = (const float*)d_in[4];
    const float* gate_w = (const float*)d_in[5];
    const float* a1     = (const float*)d_in[6];
    const float* b1     = (const float*)d_in[7];
    const float* a3     = (const float*)d_in[8];
    const float* b3     = (const float*)d_in[9];
    const float* a2     = (const float*)d_in[10];
    const float* b2     = (const float*)d_in[11];
    float* out = (float*)d_out;

    const int ETR2_SMEM = (16 + 32) * A2PITCH * 4;  // 99072
    cudaFuncSetAttribute(up_mma_kernel,
                         cudaFuncAttributeMaxDynamicSharedMemorySize, 2 * UP_STAGE);
    cudaFuncSetAttribute(down_mma_kernel,
                         cudaFuncAttributeMaxDynamicSharedMemorySize, 2 * DN_STAGE);
    cudaFuncSetAttribute(etr2_group_kernel,
                         cudaFuncAttributeMaxDynamicSharedMemorySize, ETR2_SMEM);

    cudaMemsetAsync(d_out, 0, (size_t)out_size * sizeof(float));
    cvt_kernel<<<1024, 256>>>(w1, w3, w2, a1, a3, a2);
    rmsnorm_router_kernel<<<T_TOK, 256>>>(x, norm_w, gate_w);
    sort_kernel<<<1, 256>>>();
    up_mma_kernel<<<dim3(FDIM / 128, T_TOK / 128, 2), 256, 2 * UP_STAGE>>>();
    etr_up_kernel<<<NPAIR, 256>>>();
    act_group_kernel<<<dim3(MAXG, 8), 256>>>(b1, b3);
    etr2_group_kernel<<<dim3(MAXG, 4), 256, ETR2_SMEM>>>();
    combine_kernel<<<dim3(T_TOK, 4), 256>>>();
    down_mma_kernel<<<dim3(DDIM / 128, T_TOK / 64, 2), 256, 2 * DN_STAGE>>>(b2, out);
}